// round 13
// baseline (speedup 1.0000x reference)
#include <cuda_runtime.h>
#include <cuda_bf16.h>
#include <cstdint>
#include <math.h>

typedef __nv_bfloat16  bf16;
typedef __nv_bfloat162 bf162;

// ---------------- problem constants ----------------
#define D_    512
#define H_    8
#define L_    6
#define FF_   2048
#define S_    512
#define B_    32
#define IN_   64
#define HD_   64
#define MROWS (B_ * S_)          // 16384 token rows
#define NBH   (B_ * H_)          // 256 attention batches

// ---------------- weight-plane offsets (elements) ----------------
#define OFF_INPW   0
#define OFF_INPROJ 32768
#define OFF_OUTW   4751360
#define OFF_FF1    6324224
#define OFF_FF2    12615680
#define TOTW       18907136

// ---------------- scratch (device globals; no allocation allowed) ----------------
__device__ __align__(256) float g_x   [MROWS * D_];               // activations (B,S,D)
__device__ __align__(256) float g_big [MROWS * FF_];              // ff hidden
__device__ __align__(256) float g_att [MROWS * D_];               // proj out + residual
__device__ __align__(256) float g_m   [MROWS * D_];               // merged attention output
__device__ __align__(256) float g_h   [B_ * FF_];                 // head hidden
__device__ __align__(256) bf16  g_wh  [TOTW], g_wl [TOTW];        // weight hi/lo planes
__device__ __align__(256) bf16  g_qkvh[MROWS * 3 * D_], g_qkvl[MROWS * 3 * D_];
__device__ __align__(256) bf16  g_vth [NBH * HD_ * S_], g_vtl [NBH * HD_ * S_];

// ============================================================================
// helpers
// ============================================================================
__device__ __forceinline__ uint32_t smem_u32(const void* p) {
    uint32_t a;
    asm("{ .reg .u64 t; cvta.to.shared.u64 t, %1; cvt.u32.u64 %0, t; }"
        : "=r"(a) : "l"(p));
    return a;
}

__device__ __forceinline__ void ldm4(uint32_t r[4], uint32_t addr) {
    asm volatile("ldmatrix.sync.aligned.m8n8.x4.shared.b16 {%0,%1,%2,%3}, [%4];"
                 : "=r"(r[0]), "=r"(r[1]), "=r"(r[2]), "=r"(r[3]) : "r"(addr));
}

__device__ __forceinline__ void mma_bf16(float c[4], const uint32_t a[4],
                                         const uint32_t b[2]) {
    asm volatile(
        "mma.sync.aligned.m16n8k16.row.col.f32.bf16.bf16.f32 "
        "{%0,%1,%2,%3}, {%4,%5,%6,%7}, {%8,%9}, {%0,%1,%2,%3};"
        : "+f"(c[0]), "+f"(c[1]), "+f"(c[2]), "+f"(c[3])
        : "r"(a[0]), "r"(a[1]), "r"(a[2]), "r"(a[3]), "r"(b[0]), "r"(b[1]));
}

// fp32 -> (bf16 hi, bf16 lo) convert + store 4 k-elems (8B each) at offset
__device__ __forceinline__ void cvt_st_pad(char* hi_p, char* lo_p, int off, float4 v) {
    __nv_bfloat162 h0 = __floats2bfloat162_rn(v.x, v.y);
    __nv_bfloat162 h1 = __floats2bfloat162_rn(v.z, v.w);
    float2 f0 = __bfloat1622float2(h0);
    float2 f1 = __bfloat1622float2(h1);
    __nv_bfloat162 l0 = __floats2bfloat162_rn(v.x - f0.x, v.y - f0.y);
    __nv_bfloat162 l1 = __floats2bfloat162_rn(v.z - f1.x, v.w - f1.y);
    uint2 hu, lu;
    hu.x = *(uint32_t*)&h0; hu.y = *(uint32_t*)&h1;
    lu.x = *(uint32_t*)&l0; lu.y = *(uint32_t*)&l1;
    *(uint2*)(hi_p + off) = hu;
    *(uint2*)(lo_p + off) = lu;
}

// split fp32 pair -> packed bf16 hi u32 + lo u32
__device__ __forceinline__ void split_pack(float x, float y, uint32_t& h, uint32_t& l) {
    bf162 hh = __floats2bfloat162_rn(x, y);
    float2 f = __bfloat1622float2(hh);
    bf162 ll = __floats2bfloat162_rn(x - f.x, y - f.y);
    h = *(uint32_t*)&hh;
    l = *(uint32_t*)&ll;
}

// 80-byte row stride: 32 bf16 (64B) + 16B pad -> conflict-free ldmatrix
#define RSTR 80
#define ASZ  (128 * RSTR)

// Stage 128x32 A tile (fp32 -> cvt) and 128x32 B tile (bf16 planes, pure copy)
__device__ __forceinline__ void stage_w(
    const float* __restrict__ A,
    const bf16* __restrict__ Bh, const bf16* __restrict__ Bl,
    char* buf, int m0, int n0, int k0, int lda, int ldb, int tid)
{
    char* Ahs = buf;            char* Als = buf + ASZ;
    char* Bhs = buf + 2 * ASZ;  char* Bls = Bhs + 128 * RSTR;
#pragma unroll
    for (int it = 0; it < 4; it++) {
        int idx = tid + it * 256;
        int r = idx >> 3, c4 = idx & 7;
        float4 v = *(const float4*)&A[(long long)(m0 + r) * lda + k0 + c4 * 4];
        cvt_st_pad(Ahs, Als, r * RSTR + c4 * 8, v);
    }
#pragma unroll
    for (int it = 0; it < 2; it++) {
        int id = tid + it * 256;
        int r = id >> 2, c = id & 3;
        *(uint4*)(Bhs + r * RSTR + c * 16) =
            *(const uint4*)&Bh[(long long)(n0 + r) * ldb + k0 + c * 8];
        *(uint4*)(Bls + r * RSTR + c * 16) =
            *(const uint4*)&Bl[(long long)(n0 + r) * ldb + k0 + c * 8];
    }
}

// ============================================================================
// bf16x3 mma.sync GEMM, B from pre-split bf16 hi/lo weight planes.
// C = alpha*(A @ B^T + bias) [+ residual R], optional relu.
// OM: 0 = fp32 C; 2 = bf16 hi/lo plane C with x0.125 on cols < D_ (qkv).
// CTA tile 128 x 128 x 32, 8 warps, forced 2 CTAs/SM.
// ============================================================================
template<bool BIAS, bool RELU, bool RES, int OM>
__global__ void __launch_bounds__(256, 2) gemm_w(
    const float* __restrict__ A,
    const bf16* __restrict__ Bh, const bf16* __restrict__ Bl,
    const float* __restrict__ bias, const float* __restrict__ R,
    float* __restrict__ Cf, bf16* __restrict__ Ch, bf16* __restrict__ Cl,
    int K, int lda, int ldb, int ldc, float alpha)
{
    constexpr int NNA = 4;
    constexpr int NWN = 4, WM = 64, NMA4 = 4;
    constexpr int BSZ = 128 * RSTR;
    constexpr int STAGE = 2 * ASZ + 2 * BSZ;

    extern __shared__ char smbuf[];
    const int tid = threadIdx.x, lane = tid & 31, wid = tid >> 5;

    const int m0 = blockIdx.y * 128;
    const int n0 = blockIdx.x * 128;
    const int wmb2 = (wid / NWN) * WM;
    const int wnb = (wid % NWN) * 32;

    const uint32_t sb = smem_u32(smbuf);

    float acc[NMA4][NNA][4];
#pragma unroll
    for (int i = 0; i < NMA4; i++)
#pragma unroll
        for (int j = 0; j < NNA; j++)
#pragma unroll
            for (int q = 0; q < 4; q++) acc[i][j][q] = 0.f;

    const int NKB = K >> 5;
    stage_w(A, Bh, Bl, smbuf, m0, n0, 0, lda, ldb, tid);
    __syncthreads();

    for (int kb = 0; kb < NKB; kb++) {
        const int cur = kb & 1;
        const uint32_t aH = sb + cur * STAGE;
        const uint32_t aL = aH + ASZ;
        const uint32_t bH = aH + 2 * ASZ;
        const uint32_t bL = bH + BSZ;

        const int lr = lane & 15, lh = lane >> 4;
        const int r8 = lane & 7, sel = (lane >> 3) & 1, hb = (lane >> 4) & 1;

#pragma unroll
        for (int kk = 0; kk < 32; kk += 16) {
            uint32_t ah[NMA4][4], al[NMA4][4], bh[NNA][2], bl[NNA][2];
#pragma unroll
            for (int ma = 0; ma < NMA4; ma++) {
                uint32_t row = wmb2 + ma * 16 + lr;
                uint32_t cb  = (kk + lh * 8) * 2;
                ldm4(ah[ma], aH + row * RSTR + cb);
                ldm4(al[ma], aL + row * RSTR + cb);
            }
#pragma unroll
            for (int nb = 0; nb < NNA / 2; nb++) {
                uint32_t row = wnb + nb * 16 + hb * 8 + r8;
                uint32_t cb  = (kk + sel * 8) * 2;
                uint32_t t[4];
                ldm4(t, bH + row * RSTR + cb);
                bh[2 * nb][0] = t[0]; bh[2 * nb][1] = t[1];
                bh[2 * nb + 1][0] = t[2]; bh[2 * nb + 1][1] = t[3];
                ldm4(t, bL + row * RSTR + cb);
                bl[2 * nb][0] = t[0]; bl[2 * nb][1] = t[1];
                bl[2 * nb + 1][0] = t[2]; bl[2 * nb + 1][1] = t[3];
            }
#pragma unroll
            for (int ma = 0; ma < NMA4; ma++)
#pragma unroll
                for (int na = 0; na < NNA; na++)
                    mma_bf16(acc[ma][na], ah[ma], bh[na]);
#pragma unroll
            for (int ma = 0; ma < NMA4; ma++)
#pragma unroll
                for (int na = 0; na < NNA; na++)
                    mma_bf16(acc[ma][na], ah[ma], bl[na]);
#pragma unroll
            for (int ma = 0; ma < NMA4; ma++)
#pragma unroll
                for (int na = 0; na < NNA; na++)
                    mma_bf16(acc[ma][na], al[ma], bh[na]);
        }

        if (kb + 1 < NKB)
            stage_w(A, Bh, Bl, smbuf + (cur ^ 1) * STAGE, m0, n0,
                    (kb + 1) << 5, lda, ldb, tid);
        __syncthreads();
    }

#pragma unroll
    for (int ma = 0; ma < NMA4; ma++) {
#pragma unroll
        for (int na = 0; na < NNA; na++) {
            int r = m0 + wmb2 + ma * 16 + (lane >> 2);
            int c = n0 + wnb + na * 8 + (lane & 3) * 2;
            float b0 = 0.f, b1 = 0.f;
            if (BIAS) { b0 = __ldg(&bias[c]); b1 = __ldg(&bias[c + 1]); }
#pragma unroll
            for (int half = 0; half < 2; half++) {
                int rr = r + half * 8;
                long long idx = (long long)rr * ldc + c;
                float v0 = (acc[ma][na][2 * half]     + b0) * alpha;
                float v1 = (acc[ma][na][2 * half + 1] + b1) * alpha;
                if (RELU) { v0 = fmaxf(v0, 0.f); v1 = fmaxf(v1, 0.f); }
                if (RES) {
                    float2 rv = *(const float2*)&R[idx];
                    v0 += rv.x; v1 += rv.y;
                }
                if (OM == 0) {
                    float2 fv; fv.x = v0; fv.y = v1;
                    *(float2*)&Cf[idx] = fv;
                } else {
                    if (c < D_) { v0 *= 0.125f; v1 *= 0.125f; }   // Q pre-scale
                    uint32_t hh, ll;
                    split_pack(v0, v1, hh, ll);
                    *(uint32_t*)&Ch[idx] = hh;
                    *(uint32_t*)&Cl[idx] = ll;
                }
            }
        }
    }
}

// ============================================================================
// fp32 -> bf16 hi/lo plane converter (4 elems/thread)
// ============================================================================
__global__ void cvt_plane(const float4* __restrict__ src,
                          bf162* __restrict__ h2, bf162* __restrict__ l2, int n4)
{
    int i = blockIdx.x * blockDim.x + threadIdx.x;
    if (i >= n4) return;
    float4 v = src[i];
    uint32_t h0, l0, h1, l1;
    split_pack(v.x, v.y, h0, l0);
    split_pack(v.z, v.w, h1, l1);
    ((uint32_t*)h2)[2 * i] = h0; ((uint32_t*)h2)[2 * i + 1] = h1;
    ((uint32_t*)l2)[2 * i] = l0; ((uint32_t*)l2)[2 * i + 1] = l1;
}

// ============================================================================
// fused flash attention on bf16 planes — all staging is pure 16B copies.
// Q (already x0.125 from qkv epilogue) / K from qkv planes; V from V^T planes.
// Output: fp32 merged (B,S,D).
// ============================================================================
#define QSTR 144
#define VSTR 1040
#define FL_QSZ (64 * QSTR)
#define FL_KSZ (512 * QSTR)
#define FL_VSZ (64 * VSTR)
#define FL_SMEM (2 * FL_QSZ + 2 * FL_KSZ)   // 165888

__global__ void __launch_bounds__(256, 1) flash_attn(
    const bf16* __restrict__ qh, const bf16* __restrict__ ql,
    const bf16* __restrict__ vth, const bf16* __restrict__ vtl,
    float* __restrict__ mgout)
{
    extern __shared__ char smf[];
    char* Qh = smf;              char* Ql = smf + FL_QSZ;
    char* Kh = smf + 2 * FL_QSZ; char* Kl = Kh + FL_KSZ;
    char* Vh = Kh;               char* Vl = Kh + FL_VSZ;
    float* smO = (float*)smf;
    __shared__ float smax[2][32][4], ssum[2][32][4];

    const int tid = threadIdx.x, lane = tid & 31, wid = tid >> 5;
    const int mgrp = wid >> 2, ng = wid & 3;
    const int z = blockIdx.y, s0 = blockIdx.x * 64;
    const int b = z >> 3, h = z & 7;
    const long long base = (long long)b * S_ * (3 * D_) + h * HD_;

    // ---- stage Q (64x64) and K (512x64): pure 16B copies of both planes ----
#pragma unroll
    for (int it = 0; it < 2; it++) {
        int idx = tid + it * 256;
        int r = idx >> 3, c = idx & 7;
        long long g = base + (long long)(s0 + r) * (3 * D_) + c * 8;
        *(uint4*)(Qh + r * QSTR + c * 16) = *(const uint4*)&qh[g];
        *(uint4*)(Ql + r * QSTR + c * 16) = *(const uint4*)&ql[g];
    }
#pragma unroll
    for (int it = 0; it < 16; it++) {
        int idx = tid + it * 256;
        int r = idx >> 3, c = idx & 7;
        long long g = base + D_ + (long long)r * (3 * D_) + c * 8;
        *(uint4*)(Kh + r * QSTR + c * 16) = *(const uint4*)&qh[g];
        *(uint4*)(Kl + r * QSTR + c * 16) = *(const uint4*)&ql[g];
    }
    __syncthreads();

    const uint32_t uQh = smem_u32(Qh), uQl = smem_u32(Ql);
    const uint32_t uKh = smem_u32(Kh), uKl = smem_u32(Kl);

    float acc[2][16][4];
#pragma unroll
    for (int i = 0; i < 2; i++)
#pragma unroll
        for (int j = 0; j < 16; j++)
#pragma unroll
            for (int q = 0; q < 4; q++) acc[i][j][q] = 0.f;

    const int lr = lane & 15, lh = lane >> 4;
    const int r8 = lane & 7, sel = (lane >> 3) & 1, hb = (lane >> 4) & 1;

#pragma unroll
    for (int kc = 0; kc < 4; kc++) {
        const int kk = kc * 16;
        uint32_t ah[2][4], al[2][4];
#pragma unroll
        for (int ma = 0; ma < 2; ma++) {
            uint32_t rowA = mgrp * 32 + ma * 16 + lr;
            uint32_t cb = (kk + lh * 8) * 2;
            ldm4(ah[ma], uQh + rowA * QSTR + cb);
            ldm4(al[ma], uQl + rowA * QSTR + cb);
        }
#pragma unroll
        for (int half = 0; half < 2; half++) {
            uint32_t bh[8][2], bl[8][2];
#pragma unroll
            for (int p = 0; p < 4; p++) {
                uint32_t rowB = ng * 128 + (half * 4 + p) * 16 + hb * 8 + r8;
                uint32_t cb = (kk + sel * 8) * 2;
                uint32_t t[4];
                ldm4(t, uKh + rowB * QSTR + cb);
                bh[2 * p][0] = t[0]; bh[2 * p][1] = t[1];
                bh[2 * p + 1][0] = t[2]; bh[2 * p + 1][1] = t[3];
                ldm4(t, uKl + rowB * QSTR + cb);
                bl[2 * p][0] = t[0]; bl[2 * p][1] = t[1];
                bl[2 * p + 1][0] = t[2]; bl[2 * p + 1][1] = t[3];
            }
#pragma unroll
            for (int ma = 0; ma < 2; ma++)
#pragma unroll
                for (int q = 0; q < 8; q++)
                    mma_bf16(acc[ma][half * 8 + q], ah[ma], bh[q]);
#pragma unroll
            for (int ma = 0; ma < 2; ma++)
#pragma unroll
                for (int q = 0; q < 8; q++)
                    mma_bf16(acc[ma][half * 8 + q], ah[ma], bl[q]);
#pragma unroll
            for (int ma = 0; ma < 2; ma++)
#pragma unroll
                for (int q = 0; q < 8; q++)
                    mma_bf16(acc[ma][half * 8 + q], al[ma], bh[q]);
        }
    }
    __syncthreads();

    // ---- stage V^T planes (64 x 512): pure copies into K region ----
#pragma unroll
    for (int it = 0; it < 16; it++) {
        int idx = tid + it * 256;
        int r = idx >> 6, c = idx & 63;
        long long g = (long long)z * (HD_ * S_) + (long long)r * S_ + c * 8;
        *(uint4*)(Vh + r * VSTR + c * 16) = *(const uint4*)&vth[g];
        *(uint4*)(Vl + r * VSTR + c * 16) = *(const uint4*)&vtl[g];
    }
#pragma unroll
    for (int i = 0; i < 16; i++) smO[tid + i * 256] = 0.f;

    float inv_[2][2];
    {
#pragma unroll
        for (int ma = 0; ma < 2; ma++)
#pragma unroll
            for (int rh = 0; rh < 2; rh++) {
                float m = -1e30f;
#pragma unroll
                for (int na = 0; na < 16; na++)
                    m = fmaxf(m, fmaxf(acc[ma][na][rh * 2], acc[ma][na][rh * 2 + 1]));
                m = fmaxf(m, __shfl_xor_sync(0xffffffffu, m, 1));
                m = fmaxf(m, __shfl_xor_sync(0xffffffffu, m, 2));
                if ((lane & 3) == 0)
                    smax[mgrp][ma * 16 + rh * 8 + (lane >> 2)][ng] = m;
            }
        __syncthreads();
#pragma unroll
        for (int ma = 0; ma < 2; ma++)
#pragma unroll
            for (int rh = 0; rh < 2; rh++) {
                int rrow = ma * 16 + rh * 8 + (lane >> 2);
                float gm = fmaxf(fmaxf(smax[mgrp][rrow][0], smax[mgrp][rrow][1]),
                                 fmaxf(smax[mgrp][rrow][2], smax[mgrp][rrow][3]));
                float s = 0.f;
#pragma unroll
                for (int na = 0; na < 16; na++) {
                    float e0 = __expf(acc[ma][na][rh * 2]     - gm);
                    float e1 = __expf(acc[ma][na][rh * 2 + 1] - gm);
                    acc[ma][na][rh * 2]     = e0;
                    acc[ma][na][rh * 2 + 1] = e1;
                    s += e0 + e1;
                }
                s += __shfl_xor_sync(0xffffffffu, s, 1);
                s += __shfl_xor_sync(0xffffffffu, s, 2);
                if ((lane & 3) == 0)
                    ssum[mgrp][rrow][ng] = s;
            }
        __syncthreads();
#pragma unroll
        for (int ma = 0; ma < 2; ma++)
#pragma unroll
            for (int rh = 0; rh < 2; rh++) {
                int rrow = ma * 16 + rh * 8 + (lane >> 2);
                float gs = ssum[mgrp][rrow][0] + ssum[mgrp][rrow][1] +
                           ssum[mgrp][rrow][2] + ssum[mgrp][rrow][3];
                inv_[ma][rh] = 1.f / gs;
            }
#pragma unroll
        for (int ma = 0; ma < 2; ma++)
#pragma unroll
            for (int na = 0; na < 16; na++)
#pragma unroll
                for (int rh = 0; rh < 2; rh++) {
                    acc[ma][na][rh * 2]     *= inv_[ma][rh];
                    acc[ma][na][rh * 2 + 1] *= inv_[ma][rh];
                }
    }

    float oacc[2][8][4];
#pragma unroll
    for (int i = 0; i < 2; i++)
#pragma unroll
        for (int j = 0; j < 8; j++)
#pragma unroll
            for (int q = 0; q < 4; q++) oacc[i][j][q] = 0.f;

    const uint32_t uVh = smem_u32(Vh), uVl = smem_u32(Vl);
#pragma unroll
    for (int j = 0; j < 8; j++) {
        uint32_t ah2[2][4], al2[2][4];
#pragma unroll
        for (int ma = 0; ma < 2; ma++) {
            split_pack(acc[ma][2 * j][0],     acc[ma][2 * j][1],     ah2[ma][0], al2[ma][0]);
            split_pack(acc[ma][2 * j][2],     acc[ma][2 * j][3],     ah2[ma][1], al2[ma][1]);
            split_pack(acc[ma][2 * j + 1][0], acc[ma][2 * j + 1][1], ah2[ma][2], al2[ma][2]);
            split_pack(acc[ma][2 * j + 1][2], acc[ma][2 * j + 1][3], ah2[ma][3], al2[ma][3]);
        }
        uint32_t bh[8][2], bl[8][2];
#pragma unroll
        for (int p = 0; p < 4; p++) {
            uint32_t rowB = p * 16 + hb * 8 + r8;
            uint32_t cb = (ng * 128 + j * 16 + sel * 8) * 2;
            uint32_t t[4];
            ldm4(t, uVh + rowB * VSTR + cb);
            bh[2 * p][0] = t[0]; bh[2 * p][1] = t[1];
            bh[2 * p + 1][0] = t[2]; bh[2 * p + 1][1] = t[3];
            ldm4(t, uVl + rowB * VSTR + cb);
            bl[2 * p][0] = t[0]; bl[2 * p][1] = t[1];
            bl[2 * p + 1][0] = t[2]; bl[2 * p + 1][1] = t[3];
        }
#pragma unroll
        for (int ma = 0; ma < 2; ma++)
#pragma unroll
            for (int q = 0; q < 8; q++)
                mma_bf16(oacc[ma][q], ah2[ma], bh[q]);
#pragma unroll
        for (int ma = 0; ma < 2; ma++)
#pragma unroll
            for (int q = 0; q < 8; q++)
                mma_bf16(oacc[ma][q], ah2[ma], bl[q]);
#pragma unroll
        for (int ma = 0; ma < 2; ma++)
#pragma unroll
            for (int q = 0; q < 8; q++)
                mma_bf16(oacc[ma][q], al2[ma], bh[q]);
    }

    for (int w = 0; w < 4; w++) {
        __syncthreads();
        if (ng == w) {
#pragma unroll
            for (int ma = 0; ma < 2; ma++)
#pragma unroll
                for (int na = 0; na < 8; na++)
#pragma unroll
                    for (int q = 0; q < 4; q++) {
                        int row = mgrp * 32 + ma * 16 + (lane >> 2) + (q >> 1) * 8;
                        int col = na * 8 + (lane & 3) * 2 + (q & 1);
                        smO[row * 64 + col] += oacc[ma][na][q];
                    }
        }
    }
    __syncthreads();

#pragma unroll
    for (int it = 0; it < 16; it++) {
        int idx = tid + it * 256;
        int r = idx >> 6, d = idx & 63;
        mgout[(long long)b * S_ * D_ + (long long)(s0 + r) * D_ + h * HD_ + d] = smO[idx];
    }
}

// ============================================================================
// V^T on bf16 planes: vt[z][d][s] = qkv[b][s][2D + h*64 + d]
// ============================================================================
__global__ void transposeV2(const bf16* __restrict__ qh, const bf16* __restrict__ ql,
                            bf16* __restrict__ vth, bf16* __restrict__ vtl)
{
    __shared__ bf16 th[32][33], tl[32][33];
    int z = blockIdx.z;
    int s0 = blockIdx.x * 32, d0 = blockIdx.y * 32;
    int b = z >> 3, h = z & 7;
    long long sbase = (long long)b * S_ * 3 * D_ + 2 * D_ + h * HD_;
    int tx = threadIdx.x, ty = threadIdx.y;
#pragma unroll
    for (int r = 0; r < 4; r++) {
        int s = s0 + ty + r * 8;
        th[ty + r * 8][tx] = qh[sbase + (long long)s * (3 * D_) + d0 + tx];
        tl[ty + r * 8][tx] = ql[sbase + (long long)s * (3 * D_) + d0 + tx];
    }
    __syncthreads();
    long long dbase = (long long)z * HD_ * S_;
#pragma unroll
    for (int r = 0; r < 4; r++) {
        int d = d0 + ty + r * 8;
        vth[dbase + (long long)d * S_ + s0 + tx] = th[tx][ty + r * 8];
        vtl[dbase + (long long)d * S_ + s0 + tx] = tl[tx][ty + r * 8];
    }
}

// ---------------- positional encoding add ----------------
__global__ void add_pe(float* __restrict__ x)
{
    int idx = blockIdx.x * blockDim.x + threadIdx.x;
    if (idx >= MROWS * D_) return;
    int d = idx & (D_ - 1);
    int s = (idx >> 9) & (S_ - 1);
    int j2 = d & ~1;
    float ang = (float)s * expf((float)j2 * (-9.210340371976184f / (float)D_));
    x[idx] += (d & 1) ? cosf(ang) : sinf(ang);
}

// ---------------- y = LayerNorm(t) * g + b   (t already holds x + r) ----------------
__global__ __launch_bounds__(128)
void ln_only(const float* __restrict__ t_in,
             const float* __restrict__ g, const float* __restrict__ b,
             float* __restrict__ y)
{
    long long row = blockIdx.x;
    int t = threadIdx.x;
    float4 a = ((const float4*)(t_in + row * D_))[t];

    float sum = a.x + a.y + a.z + a.w;
    float sq  = a.x * a.x + a.y * a.y + a.z * a.z + a.w * a.w;
#pragma unroll
    for (int off = 16; off > 0; off >>= 1) {
        sum += __shfl_xor_sync(0xffffffffu, sum, off);
        sq  += __shfl_xor_sync(0xffffffffu, sq,  off);
    }
    __shared__ float s1[4], s2[4];
    if ((t & 31) == 0) { s1[t >> 5] = sum; s2[t >> 5] = sq; }
    __syncthreads();
    sum = s1[0] + s1[1] + s1[2] + s1[3];
    sq  = s2[0] + s2[1] + s2[2] + s2[3];

    float mean = sum * (1.f / D_);
    float var  = sq * (1.f / D_) - mean * mean;
    float inv  = rsqrtf(var + 1e-5f);

    float4 gg = ((const float4*)g)[t];
    float4 bb = ((const float4*)b)[t];
    float4 o;
    o.x = (a.x - mean) * inv * gg.x + bb.x;
    o.y = (a.y - mean) * inv * gg.y + bb.y;
    o.z = (a.z - mean) * inv * gg.z + bb.z;
    o.w = (a.w - mean) * inv * gg.w + bb.w;
    ((float4*)(y + row * D_))[t] = o;
}

// ---------------- small fp32 SGEMM for the head (M=32) ----------------
#define BMH 128
#define BNH 128
#define BKH 8
template<bool BIAS, bool RELU>
__global__ __launch_bounds__(256)
void sgemm32(const float* __restrict__ A, const float* __restrict__ B,
             const float* __restrict__ bias, float* __restrict__ C,
             int M, int N, int K, int lda, int ldb, int ldc)
{
    __shared__ float As[BKH][BMH];
    __shared__ float Bs[BKH][BNH];
    const int m0 = blockIdx.y * BMH;
    const int n0 = blockIdx.x * BNH;
    const int tid = threadIdx.x;
    const int arow = tid >> 1;
    const int acol = (tid & 1) * 4;
    const int tx = tid & 15;
    const int ty = tid >> 4;

    float acc[8][8];
#pragma unroll
    for (int i = 0; i < 8; i++)
#pragma unroll
        for (int j = 0; j < 8; j++) acc[i][j] = 0.f;

    for (int k0 = 0; k0 < K; k0 += BKH) {
        float4 av = make_float4(0.f, 0.f, 0.f, 0.f);
        if (m0 + arow < M)
            av = *(const float4*)&A[(long long)(m0 + arow) * lda + k0 + acol];
        As[acol + 0][arow] = av.x; As[acol + 1][arow] = av.y;
        As[acol + 2][arow] = av.z; As[acol + 3][arow] = av.w;
        float4 bv = make_float4(0.f, 0.f, 0.f, 0.f);
        if (n0 + arow < N)
            bv = *(const float4*)&B[(long long)(n0 + arow) * ldb + k0 + acol];
        Bs[acol + 0][arow] = bv.x; Bs[acol + 1][arow] = bv.y;
        Bs[acol + 2][arow] = bv.z; Bs[acol + 3][arow] = bv.w;
        __syncthreads();
#pragma unroll
        for (int kk = 0; kk < BKH; kk++) {
            float a[8], b[8];
            *(float4*)&a[0] = *(const float4*)&As[kk][ty * 8];
            *(float4*)&a[4] = *(const float4*)&As[kk][ty * 8 + 4];
            *(float4*)&b[0] = *(const float4*)&Bs[kk][tx * 8];
            *(float4*)&b[4] = *(const float4*)&Bs[kk][tx * 8 + 4];
#pragma unroll
            for (int i = 0; i < 8; i++)
#pragma unroll
                for (int j = 0; j < 8; j++)
                    acc[i][j] += a[i] * b[j];
        }
        __syncthreads();
    }
#pragma unroll
    for (int i = 0; i < 8; i++) {
        int row = m0 + ty * 8 + i;
        if (row >= M) continue;
#pragma unroll
        for (int j = 0; j < 8; j++) {
            int col = n0 + tx * 8 + j;
            if (col >= N) continue;
            float v = acc[i][j];
            if (BIAS) v += bias[col];
            if (RELU) v = fmaxf(v, 0.f);
            C[(long long)row * ldc + col] = v;
        }
    }
}

// ---------------- final head ----------------
__global__ __launch_bounds__(256)
void head_out(const float* __restrict__ h, const float* __restrict__ w2,
              const float* __restrict__ b2, float* __restrict__ out)
{
    int m = blockIdx.x;
    int t = threadIdx.x;
    float s = 0.f;
    for (int k = t; k < FF_; k += 256)
        s += h[m * FF_ + k] * w2[k];
#pragma unroll
    for (int off = 16; off > 0; off >>= 1)
        s += __shfl_xor_sync(0xffffffffu, s, off);
    __shared__ float sm[8];
    if ((t & 31) == 0) sm[t >> 5] = s;
    __syncthreads();
    if (t == 0) {
        float tot = 0.f;
#pragma unroll
        for (int w = 0; w < 8; w++) tot += sm[w];
        out[m] = tot + b2[0];
    }
}

// ---------------- orchestration ----------------
static constexpr int STAGE128 = 2 * ASZ + 2 * 128 * RSTR;  // 40960
static constexpr int SMEM_128 = 2 * STAGE128;               // 81920

extern "C" void kernel_launch(void* const* d_in, const int* in_sizes, int n_in,
                              void* d_out, int out_size)
{
    const float* src       = (const float*)d_in[0];
    const float* inp_w     = (const float*)d_in[1];
    const float* inp_b     = (const float*)d_in[2];
    const float* in_proj_w = (const float*)d_in[3];
    const float* in_proj_b = (const float*)d_in[4];
    const float* out_w     = (const float*)d_in[5];
    const float* out_b     = (const float*)d_in[6];
    const float* ff_w1     = (const float*)d_in[7];
    const float* ff_b1     = (const float*)d_in[8];
    const float* ff_w2     = (const float*)d_in[9];
    const float* ff_b2     = (const float*)d_in[10];
    const float* ln1_g     = (const float*)d_in[11];
    const float* ln1_b     = (const float*)d_in[12];
    const float* ln2_g     = (const float*)d_in[13];
    const float* ln2_b     = (const float*)d_in[14];
    const float* op_w1     = (const float*)d_in[15];
    const float* op_b1     = (const float*)d_in[16];
    const float* op_w2     = (const float*)d_in[17];
    const float* op_b2     = (const float*)d_in[18];
    float* out = (float*)d_out;

    float *x, *big, *att, *mg, *hh;
    bf16 *wh, *wl, *qkvh, *qkvl, *vth, *vtl;
    cudaGetSymbolAddress((void**)&x,    g_x);
    cudaGetSymbolAddress((void**)&big,  g_big);
    cudaGetSymbolAddress((void**)&att,  g_att);
    cudaGetSymbolAddress((void**)&mg,   g_m);
    cudaGetSymbolAddress((void**)&hh,   g_h);
    cudaGetSymbolAddress((void**)&wh,   g_wh);
    cudaGetSymbolAddress((void**)&wl,   g_wl);
    cudaGetSymbolAddress((void**)&qkvh, g_qkvh);
    cudaGetSymbolAddress((void**)&qkvl, g_qkvl);
    cudaGetSymbolAddress((void**)&vth,  g_vth);
    cudaGetSymbolAddress((void**)&vtl,  g_vtl);

    cudaFuncSetAttribute(gemm_w<true, false, false, 0>, cudaFuncAttributeMaxDynamicSharedMemorySize, SMEM_128);
    cudaFuncSetAttribute(gemm_w<true, true,  false, 0>, cudaFuncAttributeMaxDynamicSharedMemorySize, SMEM_128);
    cudaFuncSetAttribute(gemm_w<true, false, true,  0>, cudaFuncAttributeMaxDynamicSharedMemorySize, SMEM_128);
    cudaFuncSetAttribute(gemm_w<true, false, false, 2>, cudaFuncAttributeMaxDynamicSharedMemorySize, SMEM_128);
    cudaFuncSetAttribute(flash_attn, cudaFuncAttributeMaxDynamicSharedMemorySize, FL_SMEM);

    // ---- pre-split all weights into bf16 hi/lo planes ----
    cvt_plane<<<(32768 / 4 + 255) / 256, 256>>>(
        (const float4*)inp_w, (bf162*)(wh + OFF_INPW), (bf162*)(wl + OFF_INPW), 32768 / 4);
    cvt_plane<<<(4718592 / 4 + 255) / 256, 256>>>(
        (const float4*)in_proj_w, (bf162*)(wh + OFF_INPROJ), (bf162*)(wl + OFF_INPROJ), 4718592 / 4);
    cvt_plane<<<(1572864 / 4 + 255) / 256, 256>>>(
        (const float4*)out_w, (bf162*)(wh + OFF_OUTW), (bf162*)(wl + OFF_OUTW), 1572864 / 4);
    cvt_plane<<<(6291456 / 4 + 255) / 256, 256>>>(
        (const float4*)ff_w1, (bf162*)(wh + OFF_FF1), (bf162*)(wl + OFF_FF1), 6291456 / 4);
    cvt_plane<<<(6291456 / 4 + 255) / 256, 256>>>(
        (const float4*)ff_w2, (bf162*)(wh + OFF_FF2), (bf162*)(wl + OFF_FF2), 6291456 / 4);

    const int ELT = (MROWS * D_) / 256;

    // input projection: x = (src @ inp_w.T + inp_b) * sqrt(D)
    gemm_w<true, false, false, 0><<<dim3(4, 128, 1), 256, SMEM_128>>>(
        src, wh + OFF_INPW, wl + OFF_INPW, inp_b, nullptr,
        x, nullptr, nullptr, IN_, IN_, IN_, D_, 22.62741699796952f);
    add_pe<<<ELT, 256>>>(x);

    for (int i = 0; i < L_; i++) {
        const long long wq = OFF_INPROJ + (long long)i * 3 * D_ * D_;
        const long long wo = OFF_OUTW   + (long long)i * D_ * D_;
        const long long w1 = OFF_FF1    + (long long)i * FF_ * D_;
        const long long w2 = OFF_FF2    + (long long)i * D_ * FF_;

        // qkv -> bf16 hi/lo planes (Q cols pre-scaled by 0.125)
        gemm_w<true, false, false, 2><<<dim3(12, 128, 1), 256, SMEM_128>>>(
            x, wh + wq, wl + wq, in_proj_b + i * 3 * D_, nullptr,
            nullptr, qkvh, qkvl, D_, D_, D_, 3 * D_, 1.f);

        transposeV2<<<dim3(16, 2, NBH), dim3(32, 8)>>>(qkvh, qkvl, vth, vtl);

        // fused attention: planes in, fp32 merged out
        flash_attn<<<dim3(8, NBH), 256, FL_SMEM>>>(qkvh, qkvl, vth, vtl, mg);

        // attention out-proj with fused residual: att = mg @ W^T + b + x
        gemm_w<true, false, true, 0><<<dim3(4, 128, 1), 256, SMEM_128>>>(
            mg, wh + wo, wl + wo, out_b + i * D_, x,
            att, nullptr, nullptr, D_, D_, D_, D_, 1.f);
        ln_only<<<MROWS, 128>>>(att, ln1_g + i * D_, ln1_b + i * D_, x);

        // FFN
        gemm_w<true, true, false, 0><<<dim3(16, 128, 1), 256, SMEM_128>>>(
            x, wh + w1, wl + w1, ff_b1 + i * FF_, nullptr,
            big, nullptr, nullptr, D_, D_, D_, FF_, 1.f);
        gemm_w<true, false, true, 0><<<dim3(4, 128, 1), 256, SMEM_128>>>(
            big, wh + w2, wl + w2, ff_b2 + i * D_, x,
            att, nullptr, nullptr, FF_, FF_, FF_, D_, 1.f);
        ln_only<<<MROWS, 128>>>(att, ln2_g + i * D_, ln2_b + i * D_, x);
    }

    // head (tiny, fp32)
    sgemm32<true, true><<<dim3(16, 1, 1), 256>>>(
        x + (S_ - 1) * D_, op_w1, op_b1, hh, B_, FF_, D_, S_ * D_, D_, FF_);
    head_out<<<B_, 256>>>(hh, op_w2, op_b2, out);
}

// round 14
// speedup vs baseline: 1.5508x; 1.5508x over previous
#include <cuda_runtime.h>
#include <cuda_bf16.h>
#include <cstdint>
#include <math.h>

typedef __nv_bfloat16  bf16;
typedef __nv_bfloat162 bf162;

// ---------------- problem constants ----------------
#define D_    512
#define H_    8
#define L_    6
#define FF_   2048
#define S_    512
#define B_    32
#define IN_   64
#define HD_   64
#define MROWS (B_ * S_)          // 16384 token rows
#define NBH   (B_ * H_)          // 256 attention batches

// ---------------- weight-plane offsets (elements) ----------------
#define OFF_INPW   0
#define OFF_INPROJ 32768
#define OFF_OUTW   4751360
#define OFF_FF1    6324224
#define OFF_FF2    12615680
#define TOTW       18907136

// ---------------- scratch (device globals; no allocation allowed) ----------------
__device__ __align__(256) float g_x   [MROWS * D_];               // activations (B,S,D)
__device__ __align__(256) float g_big [MROWS * FF_];              // qkv (B,S,3D) / ff hidden
__device__ __align__(256) float g_att [MROWS * D_];               // proj out + residual
__device__ __align__(256) float g_m   [MROWS * D_];               // merged attention output
__device__ __align__(256) float g_vt  [NBH * HD_ * S_];           // V^T per (b,h): (HD,S)
__device__ __align__(256) float g_h   [B_ * FF_];                 // head hidden
__device__ __align__(256) bf16  g_wh  [TOTW], g_wl [TOTW];        // weight hi/lo planes

// ============================================================================
// helpers
// ============================================================================
__device__ __forceinline__ uint32_t smem_u32(const void* p) {
    uint32_t a;
    asm("{ .reg .u64 t; cvta.to.shared.u64 t, %1; cvt.u32.u64 %0, t; }"
        : "=r"(a) : "l"(p));
    return a;
}

__device__ __forceinline__ void ldm4(uint32_t r[4], uint32_t addr) {
    asm volatile("ldmatrix.sync.aligned.m8n8.x4.shared.b16 {%0,%1,%2,%3}, [%4];"
                 : "=r"(r[0]), "=r"(r[1]), "=r"(r[2]), "=r"(r[3]) : "r"(addr));
}

__device__ __forceinline__ void mma_bf16(float c[4], const uint32_t a[4],
                                         const uint32_t b[2]) {
    asm volatile(
        "mma.sync.aligned.m16n8k16.row.col.f32.bf16.bf16.f32 "
        "{%0,%1,%2,%3}, {%4,%5,%6,%7}, {%8,%9}, {%0,%1,%2,%3};"
        : "+f"(c[0]), "+f"(c[1]), "+f"(c[2]), "+f"(c[3])
        : "r"(a[0]), "r"(a[1]), "r"(a[2]), "r"(a[3]), "r"(b[0]), "r"(b[1]));
}

// fp32 -> (bf16 hi, bf16 lo) convert + store 4 k-elems (8B each) at offset
__device__ __forceinline__ void cvt_st_pad(char* hi_p, char* lo_p, int off, float4 v) {
    __nv_bfloat162 h0 = __floats2bfloat162_rn(v.x, v.y);
    __nv_bfloat162 h1 = __floats2bfloat162_rn(v.z, v.w);
    float2 f0 = __bfloat1622float2(h0);
    float2 f1 = __bfloat1622float2(h1);
    __nv_bfloat162 l0 = __floats2bfloat162_rn(v.x - f0.x, v.y - f0.y);
    __nv_bfloat162 l1 = __floats2bfloat162_rn(v.z - f1.x, v.w - f1.y);
    uint2 hu, lu;
    hu.x = *(uint32_t*)&h0; hu.y = *(uint32_t*)&h1;
    lu.x = *(uint32_t*)&l0; lu.y = *(uint32_t*)&l1;
    *(uint2*)(hi_p + off) = hu;
    *(uint2*)(lo_p + off) = lu;
}

// split fp32 pair -> packed bf16 hi u32 + lo u32
__device__ __forceinline__ void split_pack(float x, float y, uint32_t& h, uint32_t& l) {
    bf162 hh = __floats2bfloat162_rn(x, y);
    float2 f = __bfloat1622float2(hh);
    bf162 ll = __floats2bfloat162_rn(x - f.x, y - f.y);
    h = *(uint32_t*)&hh;
    l = *(uint32_t*)&ll;
}

// 80-byte row stride: 32 bf16 (64B) + 16B pad -> conflict-free ldmatrix
#define RSTR 80
#define ASZ  (128 * RSTR)

// Stage 128x32 A tile (fp32 -> cvt) and 128x32 B tile (bf16 planes, pure copy)
__device__ __forceinline__ void stage_w(
    const float* __restrict__ A,
    const bf16* __restrict__ Bh, const bf16* __restrict__ Bl,
    char* buf, int m0, int n0, int k0, int lda, int ldb, int tid)
{
    char* Ahs = buf;            char* Als = buf + ASZ;
    char* Bhs = buf + 2 * ASZ;  char* Bls = Bhs + 128 * RSTR;
#pragma unroll
    for (int it = 0; it < 4; it++) {
        int idx = tid + it * 256;
        int r = idx >> 3, c4 = idx & 7;
        float4 v = *(const float4*)&A[(long long)(m0 + r) * lda + k0 + c4 * 4];
        cvt_st_pad(Ahs, Als, r * RSTR + c4 * 8, v);
    }
#pragma unroll
    for (int it = 0; it < 2; it++) {
        int id = tid + it * 256;
        int r = id >> 2, c = id & 3;
        *(uint4*)(Bhs + r * RSTR + c * 16) =
            *(const uint4*)&Bh[(long long)(n0 + r) * ldb + k0 + c * 8];
        *(uint4*)(Bls + r * RSTR + c * 16) =
            *(const uint4*)&Bl[(long long)(n0 + r) * ldb + k0 + c * 8];
    }
}

// ============================================================================
// bf16x3 mma.sync GEMM, B from pre-split bf16 hi/lo weight planes.
// C = alpha*(A @ B^T + bias) [+ residual R] [+ pos-encoding], optional relu.
// CTA tile 128 x 128 x 32, 8 warps, forced 2 CTAs/SM.
// ============================================================================
template<bool BIAS, bool RELU, bool RES, bool PE>
__global__ void __launch_bounds__(256, 2) gemm_w(
    const float* __restrict__ A,
    const bf16* __restrict__ Bh, const bf16* __restrict__ Bl,
    const float* __restrict__ bias, const float* __restrict__ R,
    float* __restrict__ C,
    int K, int lda, int ldb, int ldc, float alpha)
{
    constexpr int NNA = 4;
    constexpr int NWN = 4, WM = 64, NMA4 = 4;
    constexpr int BSZ = 128 * RSTR;
    constexpr int STAGE = 2 * ASZ + 2 * BSZ;

    extern __shared__ char smbuf[];
    const int tid = threadIdx.x, lane = tid & 31, wid = tid >> 5;

    const int m0 = blockIdx.y * 128;
    const int n0 = blockIdx.x * 128;
    const int wmb2 = (wid / NWN) * WM;
    const int wnb = (wid % NWN) * 32;

    const uint32_t sb = smem_u32(smbuf);

    float acc[NMA4][NNA][4];
#pragma unroll
    for (int i = 0; i < NMA4; i++)
#pragma unroll
        for (int j = 0; j < NNA; j++)
#pragma unroll
            for (int q = 0; q < 4; q++) acc[i][j][q] = 0.f;

    const int NKB = K >> 5;
    stage_w(A, Bh, Bl, smbuf, m0, n0, 0, lda, ldb, tid);
    __syncthreads();

    for (int kb = 0; kb < NKB; kb++) {
        const int cur = kb & 1;
        const uint32_t aH = sb + cur * STAGE;
        const uint32_t aL = aH + ASZ;
        const uint32_t bH = aH + 2 * ASZ;
        const uint32_t bL = bH + BSZ;

        const int lr = lane & 15, lh = lane >> 4;
        const int r8 = lane & 7, sel = (lane >> 3) & 1, hb = (lane >> 4) & 1;

#pragma unroll
        for (int kk = 0; kk < 32; kk += 16) {
            uint32_t ah[NMA4][4], al[NMA4][4], bh[NNA][2], bl[NNA][2];
#pragma unroll
            for (int ma = 0; ma < NMA4; ma++) {
                uint32_t row = wmb2 + ma * 16 + lr;
                uint32_t cb  = (kk + lh * 8) * 2;
                ldm4(ah[ma], aH + row * RSTR + cb);
                ldm4(al[ma], aL + row * RSTR + cb);
            }
#pragma unroll
            for (int nb = 0; nb < NNA / 2; nb++) {
                uint32_t row = wnb + nb * 16 + hb * 8 + r8;
                uint32_t cb  = (kk + sel * 8) * 2;
                uint32_t t[4];
                ldm4(t, bH + row * RSTR + cb);
                bh[2 * nb][0] = t[0]; bh[2 * nb][1] = t[1];
                bh[2 * nb + 1][0] = t[2]; bh[2 * nb + 1][1] = t[3];
                ldm4(t, bL + row * RSTR + cb);
                bl[2 * nb][0] = t[0]; bl[2 * nb][1] = t[1];
                bl[2 * nb + 1][0] = t[2]; bl[2 * nb + 1][1] = t[3];
            }
#pragma unroll
            for (int ma = 0; ma < NMA4; ma++)
#pragma unroll
                for (int na = 0; na < NNA; na++)
                    mma_bf16(acc[ma][na], ah[ma], bh[na]);
#pragma unroll
            for (int ma = 0; ma < NMA4; ma++)
#pragma unroll
                for (int na = 0; na < NNA; na++)
                    mma_bf16(acc[ma][na], ah[ma], bl[na]);
#pragma unroll
            for (int ma = 0; ma < NMA4; ma++)
#pragma unroll
                for (int na = 0; na < NNA; na++)
                    mma_bf16(acc[ma][na], al[ma], bh[na]);
        }

        if (kb + 1 < NKB)
            stage_w(A, Bh, Bl, smbuf + (cur ^ 1) * STAGE, m0, n0,
                    (kb + 1) << 5, lda, ldb, tid);
        __syncthreads();
    }

#pragma unroll
    for (int ma = 0; ma < NMA4; ma++) {
#pragma unroll
        for (int na = 0; na < NNA; na++) {
            int r = m0 + wmb2 + ma * 16 + (lane >> 2);
            int c = n0 + wnb + na * 8 + (lane & 3) * 2;
            float b0 = 0.f, b1 = 0.f;
            if (BIAS) { b0 = __ldg(&bias[c]); b1 = __ldg(&bias[c + 1]); }
#pragma unroll
            for (int half = 0; half < 2; half++) {
                int rr = r + half * 8;
                long long idx = (long long)rr * ldc + c;
                float v0 = (acc[ma][na][2 * half]     + b0) * alpha;
                float v1 = (acc[ma][na][2 * half + 1] + b1) * alpha;
                if (RELU) { v0 = fmaxf(v0, 0.f); v1 = fmaxf(v1, 0.f); }
                if (RES) {
                    float2 rv = *(const float2*)&R[idx];
                    v0 += rv.x; v1 += rv.y;
                }
                if (PE) {
                    // c is even: pe(c) = sin(ang), pe(c+1) = cos(ang)
                    int s = rr & (S_ - 1);
                    float ang = (float)s *
                        expf((float)c * (-9.210340371976184f / (float)D_));
                    v0 += sinf(ang);
                    v1 += cosf(ang);
                }
                float2 fv; fv.x = v0; fv.y = v1;
                *(float2*)&C[idx] = fv;
            }
        }
    }
}

// ============================================================================
// fp32 -> bf16 hi/lo plane converter (4 elems/thread)
// ============================================================================
__global__ void cvt_plane(const float4* __restrict__ src,
                          bf162* __restrict__ h2, bf162* __restrict__ l2, int n4)
{
    int i = blockIdx.x * blockDim.x + threadIdx.x;
    if (i >= n4) return;
    float4 v = src[i];
    uint32_t h0, l0, h1, l1;
    split_pack(v.x, v.y, h0, l0);
    split_pack(v.z, v.w, h1, l1);
    ((uint32_t*)h2)[2 * i] = h0; ((uint32_t*)h2)[2 * i + 1] = h1;
    ((uint32_t*)l2)[2 * i] = l0; ((uint32_t*)l2)[2 * i + 1] = l1;
}

// ============================================================================
// fused flash attention (round-12 verbatim)
// ============================================================================
#define QSTR 144
#define VSTR 1040
#define FL_QSZ (64 * QSTR)
#define FL_KSZ (512 * QSTR)
#define FL_VSZ (64 * VSTR)
#define FL_SMEM (2 * FL_QSZ + 2 * FL_KSZ)   // 165888

__global__ void __launch_bounds__(256, 1) flash_attn(
    const float* __restrict__ qkv, const float* __restrict__ vt,
    float* __restrict__ mgout)
{
    extern __shared__ char smf[];
    char* Qh = smf;              char* Ql = smf + FL_QSZ;
    char* Kh = smf + 2 * FL_QSZ; char* Kl = Kh + FL_KSZ;
    char* Vh = Kh;               char* Vl = Kh + FL_VSZ;
    float* smO = (float*)smf;
    __shared__ float smax[2][32][4], ssum[2][32][4];

    const int tid = threadIdx.x, lane = tid & 31, wid = tid >> 5;
    const int mgrp = wid >> 2, ng = wid & 3;
    const int z = blockIdx.y, s0 = blockIdx.x * 64;
    const int b = z >> 3, h = z & 7;
    const long long base = (long long)b * S_ * (3 * D_) + h * HD_;

#pragma unroll
    for (int it = 0; it < 4; it++) {
        int idx = tid + it * 256;
        int r = idx >> 4, c4 = idx & 15;
        float4 v = *(const float4*)&qkv[base + (long long)(s0 + r) * (3 * D_) + c4 * 4];
        v.x *= 0.125f; v.y *= 0.125f; v.z *= 0.125f; v.w *= 0.125f;
        cvt_st_pad(Qh, Ql, r * QSTR + c4 * 8, v);
    }
#pragma unroll
    for (int it = 0; it < 32; it++) {
        int idx = tid + it * 256;
        int r = idx >> 4, c4 = idx & 15;
        float4 v = *(const float4*)&qkv[base + D_ + (long long)r * (3 * D_) + c4 * 4];
        cvt_st_pad(Kh, Kl, r * QSTR + c4 * 8, v);
    }
    __syncthreads();

    const uint32_t uQh = smem_u32(Qh), uQl = smem_u32(Ql);
    const uint32_t uKh = smem_u32(Kh), uKl = smem_u32(Kl);

    float acc[2][16][4];
#pragma unroll
    for (int i = 0; i < 2; i++)
#pragma unroll
        for (int j = 0; j < 16; j++)
#pragma unroll
            for (int q = 0; q < 4; q++) acc[i][j][q] = 0.f;

    const int lr = lane & 15, lh = lane >> 4;
    const int r8 = lane & 7, sel = (lane >> 3) & 1, hb = (lane >> 4) & 1;

#pragma unroll
    for (int kc = 0; kc < 4; kc++) {
        const int kk = kc * 16;
        uint32_t ah[2][4], al[2][4];
#pragma unroll
        for (int ma = 0; ma < 2; ma++) {
            uint32_t rowA = mgrp * 32 + ma * 16 + lr;
            uint32_t cb = (kk + lh * 8) * 2;
            ldm4(ah[ma], uQh + rowA * QSTR + cb);
            ldm4(al[ma], uQl + rowA * QSTR + cb);
        }
#pragma unroll
        for (int half = 0; half < 2; half++) {
            uint32_t bh[8][2], bl[8][2];
#pragma unroll
            for (int p = 0; p < 4; p++) {
                uint32_t rowB = ng * 128 + (half * 4 + p) * 16 + hb * 8 + r8;
                uint32_t cb = (kk + sel * 8) * 2;
                uint32_t t[4];
                ldm4(t, uKh + rowB * QSTR + cb);
                bh[2 * p][0] = t[0]; bh[2 * p][1] = t[1];
                bh[2 * p + 1][0] = t[2]; bh[2 * p + 1][1] = t[3];
                ldm4(t, uKl + rowB * QSTR + cb);
                bl[2 * p][0] = t[0]; bl[2 * p][1] = t[1];
                bl[2 * p + 1][0] = t[2]; bl[2 * p + 1][1] = t[3];
            }
#pragma unroll
            for (int ma = 0; ma < 2; ma++)
#pragma unroll
                for (int q = 0; q < 8; q++)
                    mma_bf16(acc[ma][half * 8 + q], ah[ma], bh[q]);
#pragma unroll
            for (int ma = 0; ma < 2; ma++)
#pragma unroll
                for (int q = 0; q < 8; q++)
                    mma_bf16(acc[ma][half * 8 + q], ah[ma], bl[q]);
#pragma unroll
            for (int ma = 0; ma < 2; ma++)
#pragma unroll
                for (int q = 0; q < 8; q++)
                    mma_bf16(acc[ma][half * 8 + q], al[ma], bh[q]);
        }
    }
    __syncthreads();

#pragma unroll
    for (int it = 0; it < 32; it++) {
        int idx = tid + it * 256;
        int r = idx >> 7, c4 = idx & 127;
        float4 v = *(const float4*)&vt[(long long)z * (HD_ * S_) + r * S_ + c4 * 4];
        cvt_st_pad(Vh, Vl, r * VSTR + c4 * 8, v);
    }
#pragma unroll
    for (int i = 0; i < 16; i++) smO[tid + i * 256] = 0.f;

    float inv_[2][2];
    {
#pragma unroll
        for (int ma = 0; ma < 2; ma++)
#pragma unroll
            for (int rh = 0; rh < 2; rh++) {
                float m = -1e30f;
#pragma unroll
                for (int na = 0; na < 16; na++)
                    m = fmaxf(m, fmaxf(acc[ma][na][rh * 2], acc[ma][na][rh * 2 + 1]));
                m = fmaxf(m, __shfl_xor_sync(0xffffffffu, m, 1));
                m = fmaxf(m, __shfl_xor_sync(0xffffffffu, m, 2));
                if ((lane & 3) == 0)
                    smax[mgrp][ma * 16 + rh * 8 + (lane >> 2)][ng] = m;
            }
        __syncthreads();
#pragma unroll
        for (int ma = 0; ma < 2; ma++)
#pragma unroll
            for (int rh = 0; rh < 2; rh++) {
                int rrow = ma * 16 + rh * 8 + (lane >> 2);
                float gm = fmaxf(fmaxf(smax[mgrp][rrow][0], smax[mgrp][rrow][1]),
                                 fmaxf(smax[mgrp][rrow][2], smax[mgrp][rrow][3]));
                float s = 0.f;
#pragma unroll
                for (int na = 0; na < 16; na++) {
                    float e0 = __expf(acc[ma][na][rh * 2]     - gm);
                    float e1 = __expf(acc[ma][na][rh * 2 + 1] - gm);
                    acc[ma][na][rh * 2]     = e0;
                    acc[ma][na][rh * 2 + 1] = e1;
                    s += e0 + e1;
                }
                s += __shfl_xor_sync(0xffffffffu, s, 1);
                s += __shfl_xor_sync(0xffffffffu, s, 2);
                if ((lane & 3) == 0)
                    ssum[mgrp][rrow][ng] = s;
            }
        __syncthreads();
#pragma unroll
        for (int ma = 0; ma < 2; ma++)
#pragma unroll
            for (int rh = 0; rh < 2; rh++) {
                int rrow = ma * 16 + rh * 8 + (lane >> 2);
                float gs = ssum[mgrp][rrow][0] + ssum[mgrp][rrow][1] +
                           ssum[mgrp][rrow][2] + ssum[mgrp][rrow][3];
                inv_[ma][rh] = 1.f / gs;
            }
#pragma unroll
        for (int ma = 0; ma < 2; ma++)
#pragma unroll
            for (int na = 0; na < 16; na++)
#pragma unroll
                for (int rh = 0; rh < 2; rh++) {
                    acc[ma][na][rh * 2]     *= inv_[ma][rh];
                    acc[ma][na][rh * 2 + 1] *= inv_[ma][rh];
                }
    }

    float oacc[2][8][4];
#pragma unroll
    for (int i = 0; i < 2; i++)
#pragma unroll
        for (int j = 0; j < 8; j++)
#pragma unroll
            for (int q = 0; q < 4; q++) oacc[i][j][q] = 0.f;

    const uint32_t uVh = smem_u32(Vh), uVl = smem_u32(Vl);
#pragma unroll
    for (int j = 0; j < 8; j++) {
        uint32_t ah2[2][4], al2[2][4];
#pragma unroll
        for (int ma = 0; ma < 2; ma++) {
            split_pack(acc[ma][2 * j][0],     acc[ma][2 * j][1],     ah2[ma][0], al2[ma][0]);
            split_pack(acc[ma][2 * j][2],     acc[ma][2 * j][3],     ah2[ma][1], al2[ma][1]);
            split_pack(acc[ma][2 * j + 1][0], acc[ma][2 * j + 1][1], ah2[ma][2], al2[ma][2]);
            split_pack(acc[ma][2 * j + 1][2], acc[ma][2 * j + 1][3], ah2[ma][3], al2[ma][3]);
        }
        uint32_t bh[8][2], bl[8][2];
#pragma unroll
        for (int p = 0; p < 4; p++) {
            uint32_t rowB = p * 16 + hb * 8 + r8;
            uint32_t cb = (ng * 128 + j * 16 + sel * 8) * 2;
            uint32_t t[4];
            ldm4(t, uVh + rowB * VSTR + cb);
            bh[2 * p][0] = t[0]; bh[2 * p][1] = t[1];
            bh[2 * p + 1][0] = t[2]; bh[2 * p + 1][1] = t[3];
            ldm4(t, uVl + rowB * VSTR + cb);
            bl[2 * p][0] = t[0]; bl[2 * p][1] = t[1];
            bl[2 * p + 1][0] = t[2]; bl[2 * p + 1][1] = t[3];
        }
#pragma unroll
        for (int ma = 0; ma < 2; ma++)
#pragma unroll
            for (int q = 0; q < 8; q++)
                mma_bf16(oacc[ma][q], ah2[ma], bh[q]);
#pragma unroll
        for (int ma = 0; ma < 2; ma++)
#pragma unroll
            for (int q = 0; q < 8; q++)
                mma_bf16(oacc[ma][q], ah2[ma], bl[q]);
#pragma unroll
        for (int ma = 0; ma < 2; ma++)
#pragma unroll
            for (int q = 0; q < 8; q++)
                mma_bf16(oacc[ma][q], al2[ma], bh[q]);
    }

    for (int w = 0; w < 4; w++) {
        __syncthreads();
        if (ng == w) {
#pragma unroll
            for (int ma = 0; ma < 2; ma++)
#pragma unroll
                for (int na = 0; na < 8; na++)
#pragma unroll
                    for (int q = 0; q < 4; q++) {
                        int row = mgrp * 32 + ma * 16 + (lane >> 2) + (q >> 1) * 8;
                        int col = na * 8 + (lane & 3) * 2 + (q & 1);
                        smO[row * 64 + col] += oacc[ma][na][q];
                    }
        }
    }
    __syncthreads();

#pragma unroll
    for (int it = 0; it < 16; it++) {
        int idx = tid + it * 256;
        int r = idx >> 6, d = idx & 63;
        mgout[(long long)b * S_ * D_ + (long long)(s0 + r) * D_ + h * HD_ + d] = smO[idx];
    }
}

// ============================================================================
// V^T per (b,h): vt[z][hd][s] = qkv[b][s][2D + h*64 + hd]   (fp32)
// ============================================================================
__global__ void transposeV(const float* __restrict__ qkv, float* __restrict__ vt)
{
    __shared__ float t[32][33];
    int z = blockIdx.z;
    int s0 = blockIdx.x * 32, d0 = blockIdx.y * 32;
    int b = z >> 3, h = z & 7;
    const float* src = qkv + (long long)b * S_ * 3 * D_ + 2 * D_ + h * HD_;
    int tx = threadIdx.x, ty = threadIdx.y;
#pragma unroll
    for (int r = 0; r < 4; r++) {
        int s = s0 + ty + r * 8;
        t[ty + r * 8][tx] = src[(long long)s * (3 * D_) + d0 + tx];
    }
    __syncthreads();
    float* dst = vt + (long long)z * HD_ * S_;
#pragma unroll
    for (int r = 0; r < 4; r++) {
        int d = d0 + ty + r * 8;
        dst[(long long)d * S_ + s0 + tx] = t[tx][ty + r * 8];
    }
}

// ---------------- y = LayerNorm(t) * g + b   (t already holds x + r) ----------------
__global__ __launch_bounds__(128)
void ln_only(const float* __restrict__ t_in,
             const float* __restrict__ g, const float* __restrict__ b,
             float* __restrict__ y)
{
    long long row = blockIdx.x;
    int t = threadIdx.x;
    float4 a = ((const float4*)(t_in + row * D_))[t];

    float sum = a.x + a.y + a.z + a.w;
    float sq  = a.x * a.x + a.y * a.y + a.z * a.z + a.w * a.w;
#pragma unroll
    for (int off = 16; off > 0; off >>= 1) {
        sum += __shfl_xor_sync(0xffffffffu, sum, off);
        sq  += __shfl_xor_sync(0xffffffffu, sq,  off);
    }
    __shared__ float s1[4], s2[4];
    if ((t & 31) == 0) { s1[t >> 5] = sum; s2[t >> 5] = sq; }
    __syncthreads();
    sum = s1[0] + s1[1] + s1[2] + s1[3];
    sq  = s2[0] + s2[1] + s2[2] + s2[3];

    float mean = sum * (1.f / D_);
    float var  = sq * (1.f / D_) - mean * mean;
    float inv  = rsqrtf(var + 1e-5f);

    float4 gg = ((const float4*)g)[t];
    float4 bb = ((const float4*)b)[t];
    float4 o;
    o.x = (a.x - mean) * inv * gg.x + bb.x;
    o.y = (a.y - mean) * inv * gg.y + bb.y;
    o.z = (a.z - mean) * inv * gg.z + bb.z;
    o.w = (a.w - mean) * inv * gg.w + bb.w;
    ((float4*)(y + row * D_))[t] = o;
}

// ---------------- small fp32 SGEMM for the head (M=32) ----------------
#define BMH 128
#define BNH 128
#define BKH 8
template<bool BIAS, bool RELU>
__global__ __launch_bounds__(256)
void sgemm32(const float* __restrict__ A, const float* __restrict__ B,
             const float* __restrict__ bias, float* __restrict__ C,
             int M, int N, int K, int lda, int ldb, int ldc)
{
    __shared__ float As[BKH][BMH];
    __shared__ float Bs[BKH][BNH];
    const int m0 = blockIdx.y * BMH;
    const int n0 = blockIdx.x * BNH;
    const int tid = threadIdx.x;
    const int arow = tid >> 1;
    const int acol = (tid & 1) * 4;
    const int tx = tid & 15;
    const int ty = tid >> 4;

    float acc[8][8];
#pragma unroll
    for (int i = 0; i < 8; i++)
#pragma unroll
        for (int j = 0; j < 8; j++) acc[i][j] = 0.f;

    for (int k0 = 0; k0 < K; k0 += BKH) {
        float4 av = make_float4(0.f, 0.f, 0.f, 0.f);
        if (m0 + arow < M)
            av = *(const float4*)&A[(long long)(m0 + arow) * lda + k0 + acol];
        As[acol + 0][arow] = av.x; As[acol + 1][arow] = av.y;
        As[acol + 2][arow] = av.z; As[acol + 3][arow] = av.w;
        float4 bv = make_float4(0.f, 0.f, 0.f, 0.f);
        if (n0 + arow < N)
            bv = *(const float4*)&B[(long long)(n0 + arow) * ldb + k0 + acol];
        Bs[acol + 0][arow] = bv.x; Bs[acol + 1][arow] = bv.y;
        Bs[acol + 2][arow] = bv.z; Bs[acol + 3][arow] = bv.w;
        __syncthreads();
#pragma unroll
        for (int kk = 0; kk < BKH; kk++) {
            float a[8], b[8];
            *(float4*)&a[0] = *(const float4*)&As[kk][ty * 8];
            *(float4*)&a[4] = *(const float4*)&As[kk][ty * 8 + 4];
            *(float4*)&b[0] = *(const float4*)&Bs[kk][tx * 8];
            *(float4*)&b[4] = *(const float4*)&Bs[kk][tx * 8 + 4];
#pragma unroll
            for (int i = 0; i < 8; i++)
#pragma unroll
                for (int j = 0; j < 8; j++)
                    acc[i][j] += a[i] * b[j];
        }
        __syncthreads();
    }
#pragma unroll
    for (int i = 0; i < 8; i++) {
        int row = m0 + ty * 8 + i;
        if (row >= M) continue;
#pragma unroll
        for (int j = 0; j < 8; j++) {
            int col = n0 + tx * 8 + j;
            if (col >= N) continue;
            float v = acc[i][j];
            if (BIAS) v += bias[col];
            if (RELU) v = fmaxf(v, 0.f);
            C[(long long)row * ldc + col] = v;
        }
    }
}

// ---------------- final head ----------------
__global__ __launch_bounds__(256)
void head_out(const float* __restrict__ h, const float* __restrict__ w2,
              const float* __restrict__ b2, float* __restrict__ out)
{
    int m = blockIdx.x;
    int t = threadIdx.x;
    float s = 0.f;
    for (int k = t; k < FF_; k += 256)
        s += h[m * FF_ + k] * w2[k];
#pragma unroll
    for (int off = 16; off > 0; off >>= 1)
        s += __shfl_xor_sync(0xffffffffu, s, off);
    __shared__ float sm[8];
    if ((t & 31) == 0) sm[t >> 5] = s;
    __syncthreads();
    if (t == 0) {
        float tot = 0.f;
#pragma unroll
        for (int w = 0; w < 8; w++) tot += sm[w];
        out[m] = tot + b2[0];
    }
}

// ---------------- orchestration ----------------
static constexpr int STAGE128 = 2 * ASZ + 2 * 128 * RSTR;  // 40960
static constexpr int SMEM_128 = 2 * STAGE128;               // 81920

extern "C" void kernel_launch(void* const* d_in, const int* in_sizes, int n_in,
                              void* d_out, int out_size)
{
    const float* src       = (const float*)d_in[0];
    const float* inp_w     = (const float*)d_in[1];
    const float* inp_b     = (const float*)d_in[2];
    const float* in_proj_w = (const float*)d_in[3];
    const float* in_proj_b = (const float*)d_in[4];
    const float* out_w     = (const float*)d_in[5];
    const float* out_b     = (const float*)d_in[6];
    const float* ff_w1     = (const float*)d_in[7];
    const float* ff_b1     = (const float*)d_in[8];
    const float* ff_w2     = (const float*)d_in[9];
    const float* ff_b2     = (const float*)d_in[10];
    const float* ln1_g     = (const float*)d_in[11];
    const float* ln1_b     = (const float*)d_in[12];
    const float* ln2_g     = (const float*)d_in[13];
    const float* ln2_b     = (const float*)d_in[14];
    const float* op_w1     = (const float*)d_in[15];
    const float* op_b1     = (const float*)d_in[16];
    const float* op_w2     = (const float*)d_in[17];
    const float* op_b2     = (const float*)d_in[18];
    float* out = (float*)d_out;

    float *x, *big, *att, *mg, *vt, *hh;
    bf16 *wh, *wl;
    cudaGetSymbolAddress((void**)&x,   g_x);
    cudaGetSymbolAddress((void**)&big, g_big);
    cudaGetSymbolAddress((void**)&att, g_att);
    cudaGetSymbolAddress((void**)&mg,  g_m);
    cudaGetSymbolAddress((void**)&vt,  g_vt);
    cudaGetSymbolAddress((void**)&hh,  g_h);
    cudaGetSymbolAddress((void**)&wh,  g_wh);
    cudaGetSymbolAddress((void**)&wl,  g_wl);

    cudaFuncSetAttribute(gemm_w<true, false, false, false>, cudaFuncAttributeMaxDynamicSharedMemorySize, SMEM_128);
    cudaFuncSetAttribute(gemm_w<true, true,  false, false>, cudaFuncAttributeMaxDynamicSharedMemorySize, SMEM_128);
    cudaFuncSetAttribute(gemm_w<true, false, true,  false>, cudaFuncAttributeMaxDynamicSharedMemorySize, SMEM_128);
    cudaFuncSetAttribute(gemm_w<true, false, false, true >, cudaFuncAttributeMaxDynamicSharedMemorySize, SMEM_128);
    cudaFuncSetAttribute(flash_attn, cudaFuncAttributeMaxDynamicSharedMemorySize, FL_SMEM);

    // ---- pre-split all weights into bf16 hi/lo planes ----
    cvt_plane<<<(32768 / 4 + 255) / 256, 256>>>(
        (const float4*)inp_w, (bf162*)(wh + OFF_INPW), (bf162*)(wl + OFF_INPW), 32768 / 4);
    cvt_plane<<<(4718592 / 4 + 255) / 256, 256>>>(
        (const float4*)in_proj_w, (bf162*)(wh + OFF_INPROJ), (bf162*)(wl + OFF_INPROJ), 4718592 / 4);
    cvt_plane<<<(1572864 / 4 + 255) / 256, 256>>>(
        (const float4*)out_w, (bf162*)(wh + OFF_OUTW), (bf162*)(wl + OFF_OUTW), 1572864 / 4);
    cvt_plane<<<(6291456 / 4 + 255) / 256, 256>>>(
        (const float4*)ff_w1, (bf162*)(wh + OFF_FF1), (bf162*)(wl + OFF_FF1), 6291456 / 4);
    cvt_plane<<<(6291456 / 4 + 255) / 256, 256>>>(
        (const float4*)ff_w2, (bf162*)(wh + OFF_FF2), (bf162*)(wl + OFF_FF2), 6291456 / 4);

    // input projection with fused positional encoding:
    // x = (src @ inp_w.T + inp_b) * sqrt(D) + pe
    gemm_w<true, false, false, true><<<dim3(4, 128, 1), 256, SMEM_128>>>(
        src, wh + OFF_INPW, wl + OFF_INPW, inp_b, nullptr, x,
        IN_, IN_, IN_, D_, 22.62741699796952f);

    for (int i = 0; i < L_; i++) {
        const long long wq = OFF_INPROJ + (long long)i * 3 * D_ * D_;
        const long long wo = OFF_OUTW   + (long long)i * D_ * D_;
        const long long w1 = OFF_FF1    + (long long)i * FF_ * D_;
        const long long w2 = OFF_FF2    + (long long)i * D_ * FF_;

        // qkv = x @ in_proj_w[i].T + in_proj_b[i]   -> big (B,S,3D)
        gemm_w<true, false, false, false><<<dim3(12, 128, 1), 256, SMEM_128>>>(
            x, wh + wq, wl + wq, in_proj_b + i * 3 * D_, nullptr, big,
            D_, D_, D_, 3 * D_, 1.f);

        transposeV<<<dim3(16, 2, NBH), dim3(32, 8)>>>(big, vt);

        // fused attention: scores + softmax + PV -> merged (B,S,D)
        flash_attn<<<dim3(8, NBH), 256, FL_SMEM>>>(big, vt, mg);

        // attention out-proj with fused residual: att = mg @ W^T + b + x
        gemm_w<true, false, true, false><<<dim3(4, 128, 1), 256, SMEM_128>>>(
            mg, wh + wo, wl + wo, out_b + i * D_, x, att,
            D_, D_, D_, D_, 1.f);
        ln_only<<<MROWS, 128>>>(att, ln1_g + i * D_, ln1_b + i * D_, x);

        // FFN
        gemm_w<true, true, false, false><<<dim3(16, 128, 1), 256, SMEM_128>>>(
            x, wh + w1, wl + w1, ff_b1 + i * FF_, nullptr, big,
            D_, D_, D_, FF_, 1.f);
        // FF2 with fused residual: att = big @ W2^T + b + x
        gemm_w<true, false, true, false><<<dim3(4, 128, 1), 256, SMEM_128>>>(
            big, wh + w2, wl + w2, ff_b2 + i * D_, x, att,
            FF_, FF_, FF_, D_, 1.f);
        ln_only<<<MROWS, 128>>>(att, ln2_g + i * D_, ln2_b + i * D_, x);
    }

    // head (tiny, fp32)
    sgemm32<true, true><<<dim3(16, 1, 1), 256>>>(
        x + (S_ - 1) * D_, op_w1, op_b1, hh, B_, FF_, D_, S_ * D_, D_, FF_);
    head_out<<<B_, 256>>>(hh, op_w2, op_b2, out);
}

// round 15
// speedup vs baseline: 1.5558x; 1.0032x over previous
#include <cuda_runtime.h>
#include <cuda_bf16.h>
#include <cstdint>
#include <math.h>

typedef __nv_bfloat16  bf16;
typedef __nv_bfloat162 bf162;

// ---------------- problem constants ----------------
#define D_    512
#define H_    8
#define L_    6
#define FF_   2048
#define S_    512
#define B_    32
#define IN_   64
#define HD_   64
#define MROWS (B_ * S_)          // 16384 token rows
#define NBH   (B_ * H_)          // 256 attention batches

// ---------------- weight-plane offsets (elements) ----------------
#define OFF_INPW   0
#define OFF_INPROJ 32768
#define OFF_OUTW   4751360
#define OFF_FF1    6324224
#define OFF_FF2    12615680
#define TOTW       18907136

// ---------------- scratch (device globals; no allocation allowed) ----------------
__device__ __align__(256) float g_x   [MROWS * D_];               // activations (B,S,D)
__device__ __align__(256) float g_big [MROWS * FF_];              // qkv (B,S,3D) / ff hidden
__device__ __align__(256) float g_att [MROWS * D_];               // proj out + residual
__device__ __align__(256) float g_m   [MROWS * D_];               // merged attention output
__device__ __align__(256) float g_h   [B_ * FF_];                 // head hidden
__device__ __align__(256) bf16  g_wh  [TOTW], g_wl [TOTW];        // weight hi/lo planes
__device__ __align__(256) bf16  g_vth [NBH * HD_ * S_];           // V^T hi plane
__device__ __align__(256) bf16  g_vtl [NBH * HD_ * S_];           // V^T lo plane

// ============================================================================
// helpers
// ============================================================================
__device__ __forceinline__ uint32_t smem_u32(const void* p) {
    uint32_t a;
    asm("{ .reg .u64 t; cvta.to.shared.u64 t, %1; cvt.u32.u64 %0, t; }"
        : "=r"(a) : "l"(p));
    return a;
}

__device__ __forceinline__ void ldm4(uint32_t r[4], uint32_t addr) {
    asm volatile("ldmatrix.sync.aligned.m8n8.x4.shared.b16 {%0,%1,%2,%3}, [%4];"
                 : "=r"(r[0]), "=r"(r[1]), "=r"(r[2]), "=r"(r[3]) : "r"(addr));
}

__device__ __forceinline__ void mma_bf16(float c[4], const uint32_t a[4],
                                         const uint32_t b[2]) {
    asm volatile(
        "mma.sync.aligned.m16n8k16.row.col.f32.bf16.bf16.f32 "
        "{%0,%1,%2,%3}, {%4,%5,%6,%7}, {%8,%9}, {%0,%1,%2,%3};"
        : "+f"(c[0]), "+f"(c[1]), "+f"(c[2]), "+f"(c[3])
        : "r"(a[0]), "r"(a[1]), "r"(a[2]), "r"(a[3]), "r"(b[0]), "r"(b[1]));
}

// fp32 -> (bf16 hi, bf16 lo) convert + store 4 k-elems (8B each) at offset
__device__ __forceinline__ void cvt_st_pad(char* hi_p, char* lo_p, int off, float4 v) {
    __nv_bfloat162 h0 = __floats2bfloat162_rn(v.x, v.y);
    __nv_bfloat162 h1 = __floats2bfloat162_rn(v.z, v.w);
    float2 f0 = __bfloat1622float2(h0);
    float2 f1 = __bfloat1622float2(h1);
    __nv_bfloat162 l0 = __floats2bfloat162_rn(v.x - f0.x, v.y - f0.y);
    __nv_bfloat162 l1 = __floats2bfloat162_rn(v.z - f1.x, v.w - f1.y);
    uint2 hu, lu;
    hu.x = *(uint32_t*)&h0; hu.y = *(uint32_t*)&h1;
    lu.x = *(uint32_t*)&l0; lu.y = *(uint32_t*)&l1;
    *(uint2*)(hi_p + off) = hu;
    *(uint2*)(lo_p + off) = lu;
}

// split fp32 pair -> packed bf16 hi u32 + lo u32
__device__ __forceinline__ void split_pack(float x, float y, uint32_t& h, uint32_t& l) {
    bf162 hh = __floats2bfloat162_rn(x, y);
    float2 f = __bfloat1622float2(hh);
    bf162 ll = __floats2bfloat162_rn(x - f.x, y - f.y);
    h = *(uint32_t*)&hh;
    l = *(uint32_t*)&ll;
}

// 80-byte row stride: 32 bf16 (64B) + 16B pad -> conflict-free ldmatrix
#define RSTR 80
#define ASZ  (128 * RSTR)

// Stage 128x32 A tile (fp32 -> cvt) and 128x32 B tile (bf16 planes, pure copy)
__device__ __forceinline__ void stage_w(
    const float* __restrict__ A,
    const bf16* __restrict__ Bh, const bf16* __restrict__ Bl,
    char* buf, int m0, int n0, int k0, int lda, int ldb, int tid)
{
    char* Ahs = buf;            char* Als = buf + ASZ;
    char* Bhs = buf + 2 * ASZ;  char* Bls = Bhs + 128 * RSTR;
#pragma unroll
    for (int it = 0; it < 4; it++) {
        int idx = tid + it * 256;
        int r = idx >> 3, c4 = idx & 7;
        float4 v = *(const float4*)&A[(long long)(m0 + r) * lda + k0 + c4 * 4];
        cvt_st_pad(Ahs, Als, r * RSTR + c4 * 8, v);
    }
#pragma unroll
    for (int it = 0; it < 2; it++) {
        int id = tid + it * 256;
        int r = id >> 2, c = id & 3;
        *(uint4*)(Bhs + r * RSTR + c * 16) =
            *(const uint4*)&Bh[(long long)(n0 + r) * ldb + k0 + c * 8];
        *(uint4*)(Bls + r * RSTR + c * 16) =
            *(const uint4*)&Bl[(long long)(n0 + r) * ldb + k0 + c * 8];
    }
}

// ============================================================================
// bf16x3 mma.sync GEMM, B from pre-split bf16 hi/lo weight planes.
// C = alpha*(A @ B^T + bias) [+ residual R] [+ pos-encoding], optional relu.
// CTA tile 128 x 128 x 32, 8 warps, forced 2 CTAs/SM.
// ============================================================================
template<bool BIAS, bool RELU, bool RES, bool PE>
__global__ void __launch_bounds__(256, 2) gemm_w(
    const float* __restrict__ A,
    const bf16* __restrict__ Bh, const bf16* __restrict__ Bl,
    const float* __restrict__ bias, const float* __restrict__ R,
    float* __restrict__ C,
    int K, int lda, int ldb, int ldc, float alpha)
{
    constexpr int NNA = 4;
    constexpr int NWN = 4, WM = 64, NMA4 = 4;
    constexpr int BSZ = 128 * RSTR;
    constexpr int STAGE = 2 * ASZ + 2 * BSZ;

    extern __shared__ char smbuf[];
    const int tid = threadIdx.x, lane = tid & 31, wid = tid >> 5;

    const int m0 = blockIdx.y * 128;
    const int n0 = blockIdx.x * 128;
    const int wmb2 = (wid / NWN) * WM;
    const int wnb = (wid % NWN) * 32;

    const uint32_t sb = smem_u32(smbuf);

    float acc[NMA4][NNA][4];
#pragma unroll
    for (int i = 0; i < NMA4; i++)
#pragma unroll
        for (int j = 0; j < NNA; j++)
#pragma unroll
            for (int q = 0; q < 4; q++) acc[i][j][q] = 0.f;

    const int NKB = K >> 5;
    stage_w(A, Bh, Bl, smbuf, m0, n0, 0, lda, ldb, tid);
    __syncthreads();

    for (int kb = 0; kb < NKB; kb++) {
        const int cur = kb & 1;
        const uint32_t aH = sb + cur * STAGE;
        const uint32_t aL = aH + ASZ;
        const uint32_t bH = aH + 2 * ASZ;
        const uint32_t bL = bH + BSZ;

        const int lr = lane & 15, lh = lane >> 4;
        const int r8 = lane & 7, sel = (lane >> 3) & 1, hb = (lane >> 4) & 1;

#pragma unroll
        for (int kk = 0; kk < 32; kk += 16) {
            uint32_t ah[NMA4][4], al[NMA4][4], bh[NNA][2], bl[NNA][2];
#pragma unroll
            for (int ma = 0; ma < NMA4; ma++) {
                uint32_t row = wmb2 + ma * 16 + lr;
                uint32_t cb  = (kk + lh * 8) * 2;
                ldm4(ah[ma], aH + row * RSTR + cb);
                ldm4(al[ma], aL + row * RSTR + cb);
            }
#pragma unroll
            for (int nb = 0; nb < NNA / 2; nb++) {
                uint32_t row = wnb + nb * 16 + hb * 8 + r8;
                uint32_t cb  = (kk + sel * 8) * 2;
                uint32_t t[4];
                ldm4(t, bH + row * RSTR + cb);
                bh[2 * nb][0] = t[0]; bh[2 * nb][1] = t[1];
                bh[2 * nb + 1][0] = t[2]; bh[2 * nb + 1][1] = t[3];
                ldm4(t, bL + row * RSTR + cb);
                bl[2 * nb][0] = t[0]; bl[2 * nb][1] = t[1];
                bl[2 * nb + 1][0] = t[2]; bl[2 * nb + 1][1] = t[3];
            }
#pragma unroll
            for (int ma = 0; ma < NMA4; ma++)
#pragma unroll
                for (int na = 0; na < NNA; na++)
                    mma_bf16(acc[ma][na], ah[ma], bh[na]);
#pragma unroll
            for (int ma = 0; ma < NMA4; ma++)
#pragma unroll
                for (int na = 0; na < NNA; na++)
                    mma_bf16(acc[ma][na], ah[ma], bl[na]);
#pragma unroll
            for (int ma = 0; ma < NMA4; ma++)
#pragma unroll
                for (int na = 0; na < NNA; na++)
                    mma_bf16(acc[ma][na], al[ma], bh[na]);
        }

        if (kb + 1 < NKB)
            stage_w(A, Bh, Bl, smbuf + (cur ^ 1) * STAGE, m0, n0,
                    (kb + 1) << 5, lda, ldb, tid);
        __syncthreads();
    }

#pragma unroll
    for (int ma = 0; ma < NMA4; ma++) {
#pragma unroll
        for (int na = 0; na < NNA; na++) {
            int r = m0 + wmb2 + ma * 16 + (lane >> 2);
            int c = n0 + wnb + na * 8 + (lane & 3) * 2;
            float b0 = 0.f, b1 = 0.f;
            if (BIAS) { b0 = __ldg(&bias[c]); b1 = __ldg(&bias[c + 1]); }
#pragma unroll
            for (int half = 0; half < 2; half++) {
                int rr = r + half * 8;
                long long idx = (long long)rr * ldc + c;
                float v0 = (acc[ma][na][2 * half]     + b0) * alpha;
                float v1 = (acc[ma][na][2 * half + 1] + b1) * alpha;
                if (RELU) { v0 = fmaxf(v0, 0.f); v1 = fmaxf(v1, 0.f); }
                if (RES) {
                    float2 rv = *(const float2*)&R[idx];
                    v0 += rv.x; v1 += rv.y;
                }
                if (PE) {
                    // c is even: pe(c) = sin(ang), pe(c+1) = cos(ang)
                    int s = rr & (S_ - 1);
                    float ang = (float)s *
                        expf((float)c * (-9.210340371976184f / (float)D_));
                    v0 += sinf(ang);
                    v1 += cosf(ang);
                }
                float2 fv; fv.x = v0; fv.y = v1;
                *(float2*)&C[idx] = fv;
            }
        }
    }
}

// ============================================================================
// fp32 -> bf16 hi/lo plane converter (4 elems/thread)
// ============================================================================
__global__ void cvt_plane(const float4* __restrict__ src,
                          bf162* __restrict__ h2, bf162* __restrict__ l2, int n4)
{
    int i = blockIdx.x * blockDim.x + threadIdx.x;
    if (i >= n4) return;
    float4 v = src[i];
    uint32_t h0, l0, h1, l1;
    split_pack(v.x, v.y, h0, l0);
    split_pack(v.z, v.w, h1, l1);
    ((uint32_t*)h2)[2 * i] = h0; ((uint32_t*)h2)[2 * i + 1] = h1;
    ((uint32_t*)l2)[2 * i] = l0; ((uint32_t*)l2)[2 * i + 1] = l1;
}

// ============================================================================
// fused flash attention. Q/K staged with cvt from fp32 qkv (as champion);
// V staged as pure 16B copies from pre-split V^T bf16 planes.
// ============================================================================
#define QSTR 144
#define VSTR 1040
#define FL_QSZ (64 * QSTR)
#define FL_KSZ (512 * QSTR)
#define FL_VSZ (64 * VSTR)
#define FL_SMEM (2 * FL_QSZ + 2 * FL_KSZ)   // 165888

__global__ void __launch_bounds__(256, 1) flash_attn(
    const float* __restrict__ qkv,
    const bf16* __restrict__ vth, const bf16* __restrict__ vtl,
    float* __restrict__ mgout)
{
    extern __shared__ char smf[];
    char* Qh = smf;              char* Ql = smf + FL_QSZ;
    char* Kh = smf + 2 * FL_QSZ; char* Kl = Kh + FL_KSZ;
    char* Vh = Kh;               char* Vl = Kh + FL_VSZ;
    float* smO = (float*)smf;
    __shared__ float smax[2][32][4], ssum[2][32][4];

    const int tid = threadIdx.x, lane = tid & 31, wid = tid >> 5;
    const int mgrp = wid >> 2, ng = wid & 3;
    const int z = blockIdx.y, s0 = blockIdx.x * 64;
    const int b = z >> 3, h = z & 7;
    const long long base = (long long)b * S_ * (3 * D_) + h * HD_;

#pragma unroll
    for (int it = 0; it < 4; it++) {
        int idx = tid + it * 256;
        int r = idx >> 4, c4 = idx & 15;
        float4 v = *(const float4*)&qkv[base + (long long)(s0 + r) * (3 * D_) + c4 * 4];
        v.x *= 0.125f; v.y *= 0.125f; v.z *= 0.125f; v.w *= 0.125f;
        cvt_st_pad(Qh, Ql, r * QSTR + c4 * 8, v);
    }
#pragma unroll
    for (int it = 0; it < 32; it++) {
        int idx = tid + it * 256;
        int r = idx >> 4, c4 = idx & 15;
        float4 v = *(const float4*)&qkv[base + D_ + (long long)r * (3 * D_) + c4 * 4];
        cvt_st_pad(Kh, Kl, r * QSTR + c4 * 8, v);
    }
    __syncthreads();

    const uint32_t uQh = smem_u32(Qh), uQl = smem_u32(Ql);
    const uint32_t uKh = smem_u32(Kh), uKl = smem_u32(Kl);

    float acc[2][16][4];
#pragma unroll
    for (int i = 0; i < 2; i++)
#pragma unroll
        for (int j = 0; j < 16; j++)
#pragma unroll
            for (int q = 0; q < 4; q++) acc[i][j][q] = 0.f;

    const int lr = lane & 15, lh = lane >> 4;
    const int r8 = lane & 7, sel = (lane >> 3) & 1, hb = (lane >> 4) & 1;

#pragma unroll
    for (int kc = 0; kc < 4; kc++) {
        const int kk = kc * 16;
        uint32_t ah[2][4], al[2][4];
#pragma unroll
        for (int ma = 0; ma < 2; ma++) {
            uint32_t rowA = mgrp * 32 + ma * 16 + lr;
            uint32_t cb = (kk + lh * 8) * 2;
            ldm4(ah[ma], uQh + rowA * QSTR + cb);
            ldm4(al[ma], uQl + rowA * QSTR + cb);
        }
#pragma unroll
        for (int half = 0; half < 2; half++) {
            uint32_t bh[8][2], bl[8][2];
#pragma unroll
            for (int p = 0; p < 4; p++) {
                uint32_t rowB = ng * 128 + (half * 4 + p) * 16 + hb * 8 + r8;
                uint32_t cb = (kk + sel * 8) * 2;
                uint32_t t[4];
                ldm4(t, uKh + rowB * QSTR + cb);
                bh[2 * p][0] = t[0]; bh[2 * p][1] = t[1];
                bh[2 * p + 1][0] = t[2]; bh[2 * p + 1][1] = t[3];
                ldm4(t, uKl + rowB * QSTR + cb);
                bl[2 * p][0] = t[0]; bl[2 * p][1] = t[1];
                bl[2 * p + 1][0] = t[2]; bl[2 * p + 1][1] = t[3];
            }
#pragma unroll
            for (int ma = 0; ma < 2; ma++)
#pragma unroll
                for (int q = 0; q < 8; q++)
                    mma_bf16(acc[ma][half * 8 + q], ah[ma], bh[q]);
#pragma unroll
            for (int ma = 0; ma < 2; ma++)
#pragma unroll
                for (int q = 0; q < 8; q++)
                    mma_bf16(acc[ma][half * 8 + q], ah[ma], bl[q]);
#pragma unroll
            for (int ma = 0; ma < 2; ma++)
#pragma unroll
                for (int q = 0; q < 8; q++)
                    mma_bf16(acc[ma][half * 8 + q], al[ma], bh[q]);
        }
    }
    __syncthreads();

    // ---- stage V^T planes (64 x 512): pure 16B copies into K region ----
#pragma unroll
    for (int it = 0; it < 16; it++) {
        int idx = tid + it * 256;
        int r = idx >> 6, c = idx & 63;
        long long g = (long long)z * (HD_ * S_) + (long long)r * S_ + c * 8;
        *(uint4*)(Vh + r * VSTR + c * 16) = *(const uint4*)&vth[g];
        *(uint4*)(Vl + r * VSTR + c * 16) = *(const uint4*)&vtl[g];
    }
#pragma unroll
    for (int i = 0; i < 16; i++) smO[tid + i * 256] = 0.f;

    float inv_[2][2];
    {
#pragma unroll
        for (int ma = 0; ma < 2; ma++)
#pragma unroll
            for (int rh = 0; rh < 2; rh++) {
                float m = -1e30f;
#pragma unroll
                for (int na = 0; na < 16; na++)
                    m = fmaxf(m, fmaxf(acc[ma][na][rh * 2], acc[ma][na][rh * 2 + 1]));
                m = fmaxf(m, __shfl_xor_sync(0xffffffffu, m, 1));
                m = fmaxf(m, __shfl_xor_sync(0xffffffffu, m, 2));
                if ((lane & 3) == 0)
                    smax[mgrp][ma * 16 + rh * 8 + (lane >> 2)][ng] = m;
            }
        __syncthreads();
#pragma unroll
        for (int ma = 0; ma < 2; ma++)
#pragma unroll
            for (int rh = 0; rh < 2; rh++) {
                int rrow = ma * 16 + rh * 8 + (lane >> 2);
                float gm = fmaxf(fmaxf(smax[mgrp][rrow][0], smax[mgrp][rrow][1]),
                                 fmaxf(smax[mgrp][rrow][2], smax[mgrp][rrow][3]));
                float s = 0.f;
#pragma unroll
                for (int na = 0; na < 16; na++) {
                    float e0 = __expf(acc[ma][na][rh * 2]     - gm);
                    float e1 = __expf(acc[ma][na][rh * 2 + 1] - gm);
                    acc[ma][na][rh * 2]     = e0;
                    acc[ma][na][rh * 2 + 1] = e1;
                    s += e0 + e1;
                }
                s += __shfl_xor_sync(0xffffffffu, s, 1);
                s += __shfl_xor_sync(0xffffffffu, s, 2);
                if ((lane & 3) == 0)
                    ssum[mgrp][rrow][ng] = s;
            }
        __syncthreads();
#pragma unroll
        for (int ma = 0; ma < 2; ma++)
#pragma unroll
            for (int rh = 0; rh < 2; rh++) {
                int rrow = ma * 16 + rh * 8 + (lane >> 2);
                float gs = ssum[mgrp][rrow][0] + ssum[mgrp][rrow][1] +
                           ssum[mgrp][rrow][2] + ssum[mgrp][rrow][3];
                inv_[ma][rh] = 1.f / gs;
            }
#pragma unroll
        for (int ma = 0; ma < 2; ma++)
#pragma unroll
            for (int na = 0; na < 16; na++)
#pragma unroll
                for (int rh = 0; rh < 2; rh++) {
                    acc[ma][na][rh * 2]     *= inv_[ma][rh];
                    acc[ma][na][rh * 2 + 1] *= inv_[ma][rh];
                }
    }

    float oacc[2][8][4];
#pragma unroll
    for (int i = 0; i < 2; i++)
#pragma unroll
        for (int j = 0; j < 8; j++)
#pragma unroll
            for (int q = 0; q < 4; q++) oacc[i][j][q] = 0.f;

    const uint32_t uVh = smem_u32(Vh), uVl = smem_u32(Vl);
#pragma unroll
    for (int j = 0; j < 8; j++) {
        uint32_t ah2[2][4], al2[2][4];
#pragma unroll
        for (int ma = 0; ma < 2; ma++) {
            split_pack(acc[ma][2 * j][0],     acc[ma][2 * j][1],     ah2[ma][0], al2[ma][0]);
            split_pack(acc[ma][2 * j][2],     acc[ma][2 * j][3],     ah2[ma][1], al2[ma][1]);
            split_pack(acc[ma][2 * j + 1][0], acc[ma][2 * j + 1][1], ah2[ma][2], al2[ma][2]);
            split_pack(acc[ma][2 * j + 1][2], acc[ma][2 * j + 1][3], ah2[ma][3], al2[ma][3]);
        }
        uint32_t bh[8][2], bl[8][2];
#pragma unroll
        for (int p = 0; p < 4; p++) {
            uint32_t rowB = p * 16 + hb * 8 + r8;
            uint32_t cb = (ng * 128 + j * 16 + sel * 8) * 2;
            uint32_t t[4];
            ldm4(t, uVh + rowB * VSTR + cb);
            bh[2 * p][0] = t[0]; bh[2 * p][1] = t[1];
            bh[2 * p + 1][0] = t[2]; bh[2 * p + 1][1] = t[3];
            ldm4(t, uVl + rowB * VSTR + cb);
            bl[2 * p][0] = t[0]; bl[2 * p][1] = t[1];
            bl[2 * p + 1][0] = t[2]; bl[2 * p + 1][1] = t[3];
        }
#pragma unroll
        for (int ma = 0; ma < 2; ma++)
#pragma unroll
            for (int q = 0; q < 8; q++)
                mma_bf16(oacc[ma][q], ah2[ma], bh[q]);
#pragma unroll
        for (int ma = 0; ma < 2; ma++)
#pragma unroll
            for (int q = 0; q < 8; q++)
                mma_bf16(oacc[ma][q], ah2[ma], bl[q]);
#pragma unroll
        for (int ma = 0; ma < 2; ma++)
#pragma unroll
            for (int q = 0; q < 8; q++)
                mma_bf16(oacc[ma][q], al2[ma], bh[q]);
    }

    for (int w = 0; w < 4; w++) {
        __syncthreads();
        if (ng == w) {
#pragma unroll
            for (int ma = 0; ma < 2; ma++)
#pragma unroll
                for (int na = 0; na < 8; na++)
#pragma unroll
                    for (int q = 0; q < 4; q++) {
                        int row = mgrp * 32 + ma * 16 + (lane >> 2) + (q >> 1) * 8;
                        int col = na * 8 + (lane & 3) * 2 + (q & 1);
                        smO[row * 64 + col] += oacc[ma][na][q];
                    }
        }
    }
    __syncthreads();

#pragma unroll
    for (int it = 0; it < 16; it++) {
        int idx = tid + it * 256;
        int r = idx >> 6, d = idx & 63;
        mgout[(long long)b * S_ * D_ + (long long)(s0 + r) * D_ + h * HD_ + d] = smO[idx];
    }
}

// ============================================================================
// V^T per (b,h) -> bf16 hi/lo planes: vt[z][d][s] = split(qkv[b][s][2D+h*64+d])
// fp32 coalesced loads (as champion's transposeV); split computed once here.
// ============================================================================
__global__ void transposeVp(const float* __restrict__ qkv,
                            bf16* __restrict__ vth, bf16* __restrict__ vtl)
{
    __shared__ bf16 th[32][33], tl[32][33];
    int z = blockIdx.z;
    int s0 = blockIdx.x * 32, d0 = blockIdx.y * 32;
    int b = z >> 3, h = z & 7;
    const float* src = qkv + (long long)b * S_ * 3 * D_ + 2 * D_ + h * HD_;
    int tx = threadIdx.x, ty = threadIdx.y;
#pragma unroll
    for (int r = 0; r < 4; r++) {
        int s = s0 + ty + r * 8;
        float v = src[(long long)s * (3 * D_) + d0 + tx];
        bf16 hi = __float2bfloat16_rn(v);
        bf16 lo = __float2bfloat16_rn(v - __bfloat162float(hi));
        th[ty + r * 8][tx] = hi;
        tl[ty + r * 8][tx] = lo;
    }
    __syncthreads();
    long long dbase = (long long)z * HD_ * S_;
#pragma unroll
    for (int r = 0; r < 4; r++) {
        int d = d0 + ty + r * 8;
        vth[dbase + (long long)d * S_ + s0 + tx] = th[tx][ty + r * 8];
        vtl[dbase + (long long)d * S_ + s0 + tx] = tl[tx][ty + r * 8];
    }
}

// ---------------- y = LayerNorm(t) * g + b   (t already holds x + r) ----------------
__global__ __launch_bounds__(128)
void ln_only(const float* __restrict__ t_in,
             const float* __restrict__ g, const float* __restrict__ b,
             float* __restrict__ y)
{
    long long row = blockIdx.x;
    int t = threadIdx.x;
    float4 a = ((const float4*)(t_in + row * D_))[t];

    float sum = a.x + a.y + a.z + a.w;
    float sq  = a.x * a.x + a.y * a.y + a.z * a.z + a.w * a.w;
#pragma unroll
    for (int off = 16; off > 0; off >>= 1) {
        sum += __shfl_xor_sync(0xffffffffu, sum, off);
        sq  += __shfl_xor_sync(0xffffffffu, sq,  off);
    }
    __shared__ float s1[4], s2[4];
    if ((t & 31) == 0) { s1[t >> 5] = sum; s2[t >> 5] = sq; }
    __syncthreads();
    sum = s1[0] + s1[1] + s1[2] + s1[3];
    sq  = s2[0] + s2[1] + s2[2] + s2[3];

    float mean = sum * (1.f / D_);
    float var  = sq * (1.f / D_) - mean * mean;
    float inv  = rsqrtf(var + 1e-5f);

    float4 gg = ((const float4*)g)[t];
    float4 bb = ((const float4*)b)[t];
    float4 o;
    o.x = (a.x - mean) * inv * gg.x + bb.x;
    o.y = (a.y - mean) * inv * gg.y + bb.y;
    o.z = (a.z - mean) * inv * gg.z + bb.z;
    o.w = (a.w - mean) * inv * gg.w + bb.w;
    ((float4*)(y + row * D_))[t] = o;
}

// ---------------- small fp32 SGEMM for the head (M=32) ----------------
#define BMH 128
#define BNH 128
#define BKH 8
template<bool BIAS, bool RELU>
__global__ __launch_bounds__(256)
void sgemm32(const float* __restrict__ A, const float* __restrict__ B,
             const float* __restrict__ bias, float* __restrict__ C,
             int M, int N, int K, int lda, int ldb, int ldc)
{
    __shared__ float As[BKH][BMH];
    __shared__ float Bs[BKH][BNH];
    const int m0 = blockIdx.y * BMH;
    const int n0 = blockIdx.x * BNH;
    const int tid = threadIdx.x;
    const int arow = tid >> 1;
    const int acol = (tid & 1) * 4;
    const int tx = tid & 15;
    const int ty = tid >> 4;

    float acc[8][8];
#pragma unroll
    for (int i = 0; i < 8; i++)
#pragma unroll
        for (int j = 0; j < 8; j++) acc[i][j] = 0.f;

    for (int k0 = 0; k0 < K; k0 += BKH) {
        float4 av = make_float4(0.f, 0.f, 0.f, 0.f);
        if (m0 + arow < M)
            av = *(const float4*)&A[(long long)(m0 + arow) * lda + k0 + acol];
        As[acol + 0][arow] = av.x; As[acol + 1][arow] = av.y;
        As[acol + 2][arow] = av.z; As[acol + 3][arow] = av.w;
        float4 bv = make_float4(0.f, 0.f, 0.f, 0.f);
        if (n0 + arow < N)
            bv = *(const float4*)&B[(long long)(n0 + arow) * ldb + k0 + acol];
        Bs[acol + 0][arow] = bv.x; Bs[acol + 1][arow] = bv.y;
        Bs[acol + 2][arow] = bv.z; Bs[acol + 3][arow] = bv.w;
        __syncthreads();
#pragma unroll
        for (int kk = 0; kk < BKH; kk++) {
            float a[8], b[8];
            *(float4*)&a[0] = *(const float4*)&As[kk][ty * 8];
            *(float4*)&a[4] = *(const float4*)&As[kk][ty * 8 + 4];
            *(float4*)&b[0] = *(const float4*)&Bs[kk][tx * 8];
            *(float4*)&b[4] = *(const float4*)&Bs[kk][tx * 8 + 4];
#pragma unroll
            for (int i = 0; i < 8; i++)
#pragma unroll
                for (int j = 0; j < 8; j++)
                    acc[i][j] += a[i] * b[j];
        }
        __syncthreads();
    }
#pragma unroll
    for (int i = 0; i < 8; i++) {
        int row = m0 + ty * 8 + i;
        if (row >= M) continue;
#pragma unroll
        for (int j = 0; j < 8; j++) {
            int col = n0 + tx * 8 + j;
            if (col >= N) continue;
            float v = acc[i][j];
            if (BIAS) v += bias[col];
            if (RELU) v = fmaxf(v, 0.f);
            C[(long long)row * ldc + col] = v;
        }
    }
}

// ---------------- final head ----------------
__global__ __launch_bounds__(256)
void head_out(const float* __restrict__ h, const float* __restrict__ w2,
              const float* __restrict__ b2, float* __restrict__ out)
{
    int m = blockIdx.x;
    int t = threadIdx.x;
    float s = 0.f;
    for (int k = t; k < FF_; k += 256)
        s += h[m * FF_ + k] * w2[k];
#pragma unroll
    for (int off = 16; off > 0; off >>= 1)
        s += __shfl_xor_sync(0xffffffffu, s, off);
    __shared__ float sm[8];
    if ((t & 31) == 0) sm[t >> 5] = s;
    __syncthreads();
    if (t == 0) {
        float tot = 0.f;
#pragma unroll
        for (int w = 0; w < 8; w++) tot += sm[w];
        out[m] = tot + b2[0];
    }
}

// ---------------- orchestration ----------------
static constexpr int STAGE128 = 2 * ASZ + 2 * 128 * RSTR;  // 40960
static constexpr int SMEM_128 = 2 * STAGE128;               // 81920

extern "C" void kernel_launch(void* const* d_in, const int* in_sizes, int n_in,
                              void* d_out, int out_size)
{
    const float* src       = (const float*)d_in[0];
    const float* inp_w     = (const float*)d_in[1];
    const float* inp_b     = (const float*)d_in[2];
    const float* in_proj_w = (const float*)d_in[3];
    const float* in_proj_b = (const float*)d_in[4];
    const float* out_w     = (const float*)d_in[5];
    const float* out_b     = (const float*)d_in[6];
    const float* ff_w1     = (const float*)d_in[7];
    const float* ff_b1     = (const float*)d_in[8];
    const float* ff_w2     = (const float*)d_in[9];
    const float* ff_b2     = (const float*)d_in[10];
    const float* ln1_g     = (const float*)d_in[11];
    const float* ln1_b     = (const float*)d_in[12];
    const float* ln2_g     = (const float*)d_in[13];
    const float* ln2_b     = (const float*)d_in[14];
    const float* op_w1     = (const float*)d_in[15];
    const float* op_b1     = (const float*)d_in[16];
    const float* op_w2     = (const float*)d_in[17];
    const float* op_b2     = (const float*)d_in[18];
    float* out = (float*)d_out;

    float *x, *big, *att, *mg, *hh;
    bf16 *wh, *wl, *vth, *vtl;
    cudaGetSymbolAddress((void**)&x,   g_x);
    cudaGetSymbolAddress((void**)&big, g_big);
    cudaGetSymbolAddress((void**)&att, g_att);
    cudaGetSymbolAddress((void**)&mg,  g_m);
    cudaGetSymbolAddress((void**)&hh,  g_h);
    cudaGetSymbolAddress((void**)&wh,  g_wh);
    cudaGetSymbolAddress((void**)&wl,  g_wl);
    cudaGetSymbolAddress((void**)&vth, g_vth);
    cudaGetSymbolAddress((void**)&vtl, g_vtl);

    cudaFuncSetAttribute(gemm_w<true, false, false, false>, cudaFuncAttributeMaxDynamicSharedMemorySize, SMEM_128);
    cudaFuncSetAttribute(gemm_w<true, true,  false, false>, cudaFuncAttributeMaxDynamicSharedMemorySize, SMEM_128);
    cudaFuncSetAttribute(gemm_w<true, false, true,  false>, cudaFuncAttributeMaxDynamicSharedMemorySize, SMEM_128);
    cudaFuncSetAttribute(gemm_w<true, false, false, true >, cudaFuncAttributeMaxDynamicSharedMemorySize, SMEM_128);
    cudaFuncSetAttribute(flash_attn, cudaFuncAttributeMaxDynamicSharedMemorySize, FL_SMEM);

    // ---- pre-split all weights into bf16 hi/lo planes ----
    cvt_plane<<<(32768 / 4 + 255) / 256, 256>>>(
        (const float4*)inp_w, (bf162*)(wh + OFF_INPW), (bf162*)(wl + OFF_INPW), 32768 / 4);
    cvt_plane<<<(4718592 / 4 + 255) / 256, 256>>>(
        (const float4*)in_proj_w, (bf162*)(wh + OFF_INPROJ), (bf162*)(wl + OFF_INPROJ), 4718592 / 4);
    cvt_plane<<<(1572864 / 4 + 255) / 256, 256>>>(
        (const float4*)out_w, (bf162*)(wh + OFF_OUTW), (bf162*)(wl + OFF_OUTW), 1572864 / 4);
    cvt_plane<<<(6291456 / 4 + 255) / 256, 256>>>(
        (const float4*)ff_w1, (bf162*)(wh + OFF_FF1), (bf162*)(wl + OFF_FF1), 6291456 / 4);
    cvt_plane<<<(6291456 / 4 + 255) / 256, 256>>>(
        (const float4*)ff_w2, (bf162*)(wh + OFF_FF2), (bf162*)(wl + OFF_FF2), 6291456 / 4);

    // input projection with fused positional encoding:
    // x = (src @ inp_w.T + inp_b) * sqrt(D) + pe
    gemm_w<true, false, false, true><<<dim3(4, 128, 1), 256, SMEM_128>>>(
        src, wh + OFF_INPW, wl + OFF_INPW, inp_b, nullptr, x,
        IN_, IN_, IN_, D_, 22.62741699796952f);

    for (int i = 0; i < L_; i++) {
        const long long wq = OFF_INPROJ + (long long)i * 3 * D_ * D_;
        const long long wo = OFF_OUTW   + (long long)i * D_ * D_;
        const long long w1 = OFF_FF1    + (long long)i * FF_ * D_;
        const long long w2 = OFF_FF2    + (long long)i * D_ * FF_;

        // qkv = x @ in_proj_w[i].T + in_proj_b[i]   -> big (B,S,3D)
        gemm_w<true, false, false, false><<<dim3(12, 128, 1), 256, SMEM_128>>>(
            x, wh + wq, wl + wq, in_proj_b + i * 3 * D_, nullptr, big,
            D_, D_, D_, 3 * D_, 1.f);

        // V^T hi/lo planes (split once here; flash copies them 8x)
        transposeVp<<<dim3(16, 2, NBH), dim3(32, 8)>>>(big, vth, vtl);

        // fused attention: scores + softmax + PV -> merged (B,S,D)
        flash_attn<<<dim3(8, NBH), 256, FL_SMEM>>>(big, vth, vtl, mg);

        // attention out-proj with fused residual: att = mg @ W^T + b + x
        gemm_w<true, false, true, false><<<dim3(4, 128, 1), 256, SMEM_128>>>(
            mg, wh + wo, wl + wo, out_b + i * D_, x, att,
            D_, D_, D_, D_, 1.f);
        ln_only<<<MROWS, 128>>>(att, ln1_g + i * D_, ln1_b + i * D_, x);

        // FFN
        gemm_w<true, true, false, false><<<dim3(16, 128, 1), 256, SMEM_128>>>(
            x, wh + w1, wl + w1, ff_b1 + i * FF_, nullptr, big,
            D_, D_, D_, FF_, 1.f);
        // FF2 with fused residual: att = big @ W2^T + b + x
        gemm_w<true, false, true, false><<<dim3(4, 128, 1), 256, SMEM_128>>>(
            big, wh + w2, wl + w2, ff_b2 + i * D_, x, att,
            FF_, FF_, FF_, D_, 1.f);
        ln_only<<<MROWS, 128>>>(att, ln2_g + i * D_, ln2_b + i * D_, x);
    }

    // head (tiny, fp32)
    sgemm32<true, true><<<dim3(16, 1, 1), 256>>>(
        x + (S_ - 1) * D_, op_w1, op_b1, hh, B_, FF_, D_, S_ * D_, D_, FF_);
    head_out<<<B_, 256>>>(hh, op_w2, op_b2, out);
}

// round 17
// speedup vs baseline: 1.6436x; 1.0565x over previous
#include <cuda_runtime.h>
#include <cuda_bf16.h>
#include <cstdint>
#include <math.h>

typedef __nv_bfloat16  bf16;
typedef __nv_bfloat162 bf162;

// ---------------- problem constants ----------------
#define D_    512
#define H_    8
#define L_    6
#define FF_   2048
#define S_    512
#define B_    32
#define IN_   64
#define HD_   64
#define MROWS (B_ * S_)          // 16384 token rows
#define NBH   (B_ * H_)          // 256 attention batches

// ---------------- weight-plane offsets (elements) ----------------
#define OFF_INPW   0
#define OFF_INPROJ 32768
#define OFF_OUTW   4751360
#define OFF_FF1    6324224
#define OFF_FF2    12615680
#define TOTW       18907136

// ---------------- scratch (device globals; no allocation allowed) ----------------
__device__ __align__(256) float g_x   [MROWS * D_];               // activations (B,S,D)
__device__ __align__(256) float g_big [MROWS * FF_];              // qkv (B,S,3D) / ff hidden
__device__ __align__(256) float g_att [MROWS * D_];               // proj out + residual
__device__ __align__(256) float g_m   [MROWS * D_];               // merged attention output
__device__ __align__(256) float g_h   [B_ * FF_];                 // head / tail hidden
__device__ __align__(256) float g_t32 [B_ * D_];                  // tail tmp (32x512)
__device__ __align__(256) float g_x32 [B_ * D_];                  // tail x (32x512)
__device__ __align__(256) bf16  g_wh  [TOTW], g_wl [TOTW];        // weight hi/lo planes
__device__ __align__(256) bf16  g_vth [NBH * HD_ * S_];           // V^T hi plane
__device__ __align__(256) bf16  g_vtl [NBH * HD_ * S_];           // V^T lo plane

// ============================================================================
// helpers
// ============================================================================
__device__ __forceinline__ uint32_t smem_u32(const void* p) {
    uint32_t a;
    asm("{ .reg .u64 t; cvta.to.shared.u64 t, %1; cvt.u32.u64 %0, t; }"
        : "=r"(a) : "l"(p));
    return a;
}

__device__ __forceinline__ void ldm4(uint32_t r[4], uint32_t addr) {
    asm volatile("ldmatrix.sync.aligned.m8n8.x4.shared.b16 {%0,%1,%2,%3}, [%4];"
                 : "=r"(r[0]), "=r"(r[1]), "=r"(r[2]), "=r"(r[3]) : "r"(addr));
}

__device__ __forceinline__ void mma_bf16(float c[4], const uint32_t a[4],
                                         const uint32_t b[2]) {
    asm volatile(
        "mma.sync.aligned.m16n8k16.row.col.f32.bf16.bf16.f32 "
        "{%0,%1,%2,%3}, {%4,%5,%6,%7}, {%8,%9}, {%0,%1,%2,%3};"
        : "+f"(c[0]), "+f"(c[1]), "+f"(c[2]), "+f"(c[3])
        : "r"(a[0]), "r"(a[1]), "r"(a[2]), "r"(a[3]), "r"(b[0]), "r"(b[1]));
}

// fp32 -> (bf16 hi, bf16 lo) convert + store 4 k-elems (8B each) at offset
__device__ __forceinline__ void cvt_st_pad(char* hi_p, char* lo_p, int off, float4 v) {
    __nv_bfloat162 h0 = __floats2bfloat162_rn(v.x, v.y);
    __nv_bfloat162 h1 = __floats2bfloat162_rn(v.z, v.w);
    float2 f0 = __bfloat1622float2(h0);
    float2 f1 = __bfloat1622float2(h1);
    __nv_bfloat162 l0 = __floats2bfloat162_rn(v.x - f0.x, v.y - f0.y);
    __nv_bfloat162 l1 = __floats2bfloat162_rn(v.z - f1.x, v.w - f1.y);
    uint2 hu, lu;
    hu.x = *(uint32_t*)&h0; hu.y = *(uint32_t*)&h1;
    lu.x = *(uint32_t*)&l0; lu.y = *(uint32_t*)&l1;
    *(uint2*)(hi_p + off) = hu;
    *(uint2*)(lo_p + off) = lu;
}

// split fp32 pair -> packed bf16 hi u32 + lo u32
__device__ __forceinline__ void split_pack(float x, float y, uint32_t& h, uint32_t& l) {
    bf162 hh = __floats2bfloat162_rn(x, y);
    float2 f = __bfloat1622float2(hh);
    bf162 ll = __floats2bfloat162_rn(x - f.x, y - f.y);
    h = *(uint32_t*)&hh;
    l = *(uint32_t*)&ll;
}

// 80-byte row stride: 32 bf16 (64B) + 16B pad -> conflict-free ldmatrix
#define RSTR 80
#define ASZ  (128 * RSTR)

// Stage 128x32 A tile (fp32 -> cvt) and 128x32 B tile (bf16 planes, pure copy)
__device__ __forceinline__ void stage_w(
    const float* __restrict__ A,
    const bf16* __restrict__ Bh, const bf16* __restrict__ Bl,
    char* buf, int m0, int n0, int k0, int lda, int ldb, int tid)
{
    char* Ahs = buf;            char* Als = buf + ASZ;
    char* Bhs = buf + 2 * ASZ;  char* Bls = Bhs + 128 * RSTR;
#pragma unroll
    for (int it = 0; it < 4; it++) {
        int idx = tid + it * 256;
        int r = idx >> 3, c4 = idx & 7;
        float4 v = *(const float4*)&A[(long long)(m0 + r) * lda + k0 + c4 * 4];
        cvt_st_pad(Ahs, Als, r * RSTR + c4 * 8, v);
    }
#pragma unroll
    for (int it = 0; it < 2; it++) {
        int id = tid + it * 256;
        int r = id >> 2, c = id & 3;
        *(uint4*)(Bhs + r * RSTR + c * 16) =
            *(const uint4*)&Bh[(long long)(n0 + r) * ldb + k0 + c * 8];
        *(uint4*)(Bls + r * RSTR + c * 16) =
            *(const uint4*)&Bl[(long long)(n0 + r) * ldb + k0 + c * 8];
    }
}

// ============================================================================
// bf16x3 mma.sync GEMM, B from pre-split bf16 hi/lo weight planes.
// C = alpha*(A @ B^T + bias) [+ residual R] [+ pos-encoding], optional relu.
// m0 = blockIdx.y * mmul + madd (row-mapping for partial-M launches).
// CTA tile 128 x 128 x 32, 8 warps, forced 2 CTAs/SM.
// ============================================================================
template<bool BIAS, bool RELU, bool RES, bool PE>
__global__ void __launch_bounds__(256, 2) gemm_w(
    const float* __restrict__ A,
    const bf16* __restrict__ Bh, const bf16* __restrict__ Bl,
    const float* __restrict__ bias, const float* __restrict__ R,
    float* __restrict__ C,
    int K, int lda, int ldb, int ldc, float alpha, int mmul, int madd)
{
    constexpr int NNA = 4;
    constexpr int NWN = 4, WM = 64, NMA4 = 4;
    constexpr int BSZ = 128 * RSTR;
    constexpr int STAGE = 2 * ASZ + 2 * BSZ;

    extern __shared__ char smbuf[];
    const int tid = threadIdx.x, lane = tid & 31, wid = tid >> 5;

    const int m0 = blockIdx.y * mmul + madd;
    const int n0 = blockIdx.x * 128;
    const int wmb2 = (wid / NWN) * WM;
    const int wnb = (wid % NWN) * 32;

    const uint32_t sb = smem_u32(smbuf);

    float acc[NMA4][NNA][4];
#pragma unroll
    for (int i = 0; i < NMA4; i++)
#pragma unroll
        for (int j = 0; j < NNA; j++)
#pragma unroll
            for (int q = 0; q < 4; q++) acc[i][j][q] = 0.f;

    const int NKB = K >> 5;
    stage_w(A, Bh, Bl, smbuf, m0, n0, 0, lda, ldb, tid);
    __syncthreads();

    for (int kb = 0; kb < NKB; kb++) {
        const int cur = kb & 1;
        const uint32_t aH = sb + cur * STAGE;
        const uint32_t aL = aH + ASZ;
        const uint32_t bH = aH + 2 * ASZ;
        const uint32_t bL = bH + BSZ;

        const int lr = lane & 15, lh = lane >> 4;
        const int r8 = lane & 7, sel = (lane >> 3) & 1, hb = (lane >> 4) & 1;

#pragma unroll
        for (int kk = 0; kk < 32; kk += 16) {
            uint32_t ah[NMA4][4], al[NMA4][4], bh[NNA][2], bl[NNA][2];
#pragma unroll
            for (int ma = 0; ma < NMA4; ma++) {
                uint32_t row = wmb2 + ma * 16 + lr;
                uint32_t cb  = (kk + lh * 8) * 2;
                ldm4(ah[ma], aH + row * RSTR + cb);
                ldm4(al[ma], aL + row * RSTR + cb);
            }
#pragma unroll
            for (int nb = 0; nb < NNA / 2; nb++) {
                uint32_t row = wnb + nb * 16 + hb * 8 + r8;
                uint32_t cb  = (kk + sel * 8) * 2;
                uint32_t t[4];
                ldm4(t, bH + row * RSTR + cb);
                bh[2 * nb][0] = t[0]; bh[2 * nb][1] = t[1];
                bh[2 * nb + 1][0] = t[2]; bh[2 * nb + 1][1] = t[3];
                ldm4(t, bL + row * RSTR + cb);
                bl[2 * nb][0] = t[0]; bl[2 * nb][1] = t[1];
                bl[2 * nb + 1][0] = t[2]; bl[2 * nb + 1][1] = t[3];
            }
#pragma unroll
            for (int ma = 0; ma < NMA4; ma++)
#pragma unroll
                for (int na = 0; na < NNA; na++)
                    mma_bf16(acc[ma][na], ah[ma], bh[na]);
#pragma unroll
            for (int ma = 0; ma < NMA4; ma++)
#pragma unroll
                for (int na = 0; na < NNA; na++)
                    mma_bf16(acc[ma][na], ah[ma], bl[na]);
#pragma unroll
            for (int ma = 0; ma < NMA4; ma++)
#pragma unroll
                for (int na = 0; na < NNA; na++)
                    mma_bf16(acc[ma][na], al[ma], bh[na]);
        }

        if (kb + 1 < NKB)
            stage_w(A, Bh, Bl, smbuf + (cur ^ 1) * STAGE, m0, n0,
                    (kb + 1) << 5, lda, ldb, tid);
        __syncthreads();
    }

#pragma unroll
    for (int ma = 0; ma < NMA4; ma++) {
#pragma unroll
        for (int na = 0; na < NNA; na++) {
            int r = m0 + wmb2 + ma * 16 + (lane >> 2);
            int c = n0 + wnb + na * 8 + (lane & 3) * 2;
            float b0 = 0.f, b1 = 0.f;
            if (BIAS) { b0 = __ldg(&bias[c]); b1 = __ldg(&bias[c + 1]); }
#pragma unroll
            for (int half = 0; half < 2; half++) {
                int rr = r + half * 8;
                long long idx = (long long)rr * ldc + c;
                float v0 = (acc[ma][na][2 * half]     + b0) * alpha;
                float v1 = (acc[ma][na][2 * half + 1] + b1) * alpha;
                if (RELU) { v0 = fmaxf(v0, 0.f); v1 = fmaxf(v1, 0.f); }
                if (RES) {
                    float2 rv = *(const float2*)&R[idx];
                    v0 += rv.x; v1 += rv.y;
                }
                if (PE) {
                    int s = rr & (S_ - 1);
                    float ang = (float)s *
                        expf((float)c * (-9.210340371976184f / (float)D_));
                    v0 += sinf(ang);
                    v1 += cosf(ang);
                }
                float2 fv; fv.x = v0; fv.y = v1;
                *(float2*)&C[idx] = fv;
            }
        }
    }
}

// ============================================================================
// fp32 -> bf16 hi/lo plane converter (4 elems/thread)
// ============================================================================
__global__ void cvt_plane(const float4* __restrict__ src,
                          bf162* __restrict__ h2, bf162* __restrict__ l2, int n4)
{
    int i = blockIdx.x * blockDim.x + threadIdx.x;
    if (i >= n4) return;
    float4 v = src[i];
    uint32_t h0, l0, h1, l1;
    split_pack(v.x, v.y, h0, l0);
    split_pack(v.z, v.w, h1, l1);
    ((uint32_t*)h2)[2 * i] = h0; ((uint32_t*)h2)[2 * i + 1] = h1;
    ((uint32_t*)l2)[2 * i] = l0; ((uint32_t*)l2)[2 * i + 1] = l1;
}

// ============================================================================
// fused flash attention (round-15 champion + s_base for partial-grid launches)
// ============================================================================
#define QSTR 144
#define VSTR 1040
#define FL_QSZ (64 * QSTR)
#define FL_KSZ (512 * QSTR)
#define FL_VSZ (64 * VSTR)
#define FL_SMEM (2 * FL_QSZ + 2 * FL_KSZ)   // 165888

__global__ void __launch_bounds__(256, 1) flash_attn(
    const float* __restrict__ qkv,
    const bf16* __restrict__ vth, const bf16* __restrict__ vtl,
    float* __restrict__ mgout, int s_base)
{
    extern __shared__ char smf[];
    char* Qh = smf;              char* Ql = smf + FL_QSZ;
    char* Kh = smf + 2 * FL_QSZ; char* Kl = Kh + FL_KSZ;
    char* Vh = Kh;               char* Vl = Kh + FL_VSZ;
    float* smO = (float*)smf;
    __shared__ float smax[2][32][4], ssum[2][32][4];

    const int tid = threadIdx.x, lane = tid & 31, wid = tid >> 5;
    const int mgrp = wid >> 2, ng = wid & 3;
    const int z = blockIdx.y, s0 = blockIdx.x * 64 + s_base;
    const int b = z >> 3, h = z & 7;
    const long long base = (long long)b * S_ * (3 * D_) + h * HD_;

#pragma unroll
    for (int it = 0; it < 4; it++) {
        int idx = tid + it * 256;
        int r = idx >> 4, c4 = idx & 15;
        float4 v = *(const float4*)&qkv[base + (long long)(s0 + r) * (3 * D_) + c4 * 4];
        v.x *= 0.125f; v.y *= 0.125f; v.z *= 0.125f; v.w *= 0.125f;
        cvt_st_pad(Qh, Ql, r * QSTR + c4 * 8, v);
    }
#pragma unroll
    for (int it = 0; it < 32; it++) {
        int idx = tid + it * 256;
        int r = idx >> 4, c4 = idx & 15;
        float4 v = *(const float4*)&qkv[base + D_ + (long long)r * (3 * D_) + c4 * 4];
        cvt_st_pad(Kh, Kl, r * QSTR + c4 * 8, v);
    }
    __syncthreads();

    const uint32_t uQh = smem_u32(Qh), uQl = smem_u32(Ql);
    const uint32_t uKh = smem_u32(Kh), uKl = smem_u32(Kl);

    float acc[2][16][4];
#pragma unroll
    for (int i = 0; i < 2; i++)
#pragma unroll
        for (int j = 0; j < 16; j++)
#pragma unroll
            for (int q = 0; q < 4; q++) acc[i][j][q] = 0.f;

    const int lr = lane & 15, lh = lane >> 4;
    const int r8 = lane & 7, sel = (lane >> 3) & 1, hb = (lane >> 4) & 1;

#pragma unroll
    for (int kc = 0; kc < 4; kc++) {
        const int kk = kc * 16;
        uint32_t ah[2][4], al[2][4];
#pragma unroll
        for (int ma = 0; ma < 2; ma++) {
            uint32_t rowA = mgrp * 32 + ma * 16 + lr;
            uint32_t cb = (kk + lh * 8) * 2;
            ldm4(ah[ma], uQh + rowA * QSTR + cb);
            ldm4(al[ma], uQl + rowA * QSTR + cb);
        }
#pragma unroll
        for (int half = 0; half < 2; half++) {
            uint32_t bh[8][2], bl[8][2];
#pragma unroll
            for (int p = 0; p < 4; p++) {
                uint32_t rowB = ng * 128 + (half * 4 + p) * 16 + hb * 8 + r8;
                uint32_t cb = (kk + sel * 8) * 2;
                uint32_t t[4];
                ldm4(t, uKh + rowB * QSTR + cb);
                bh[2 * p][0] = t[0]; bh[2 * p][1] = t[1];
                bh[2 * p + 1][0] = t[2]; bh[2 * p + 1][1] = t[3];
                ldm4(t, uKl + rowB * QSTR + cb);
                bl[2 * p][0] = t[0]; bl[2 * p][1] = t[1];
                bl[2 * p + 1][0] = t[2]; bl[2 * p + 1][1] = t[3];
            }
#pragma unroll
            for (int ma = 0; ma < 2; ma++)
#pragma unroll
                for (int q = 0; q < 8; q++)
                    mma_bf16(acc[ma][half * 8 + q], ah[ma], bh[q]);
#pragma unroll
            for (int ma = 0; ma < 2; ma++)
#pragma unroll
                for (int q = 0; q < 8; q++)
                    mma_bf16(acc[ma][half * 8 + q], ah[ma], bl[q]);
#pragma unroll
            for (int ma = 0; ma < 2; ma++)
#pragma unroll
                for (int q = 0; q < 8; q++)
                    mma_bf16(acc[ma][half * 8 + q], al[ma], bh[q]);
        }
    }
    __syncthreads();

    // ---- stage V^T planes (64 x 512): pure 16B copies into K region ----
#pragma unroll
    for (int it = 0; it < 16; it++) {
        int idx = tid + it * 256;
        int r = idx >> 6, c = idx & 63;
        long long g = (long long)z * (HD_ * S_) + (long long)r * S_ + c * 8;
        *(uint4*)(Vh + r * VSTR + c * 16) = *(const uint4*)&vth[g];
        *(uint4*)(Vl + r * VSTR + c * 16) = *(const uint4*)&vtl[g];
    }
#pragma unroll
    for (int i = 0; i < 16; i++) smO[tid + i * 256] = 0.f;

    float inv_[2][2];
    {
#pragma unroll
        for (int ma = 0; ma < 2; ma++)
#pragma unroll
            for (int rh = 0; rh < 2; rh++) {
                float m = -1e30f;
#pragma unroll
                for (int na = 0; na < 16; na++)
                    m = fmaxf(m, fmaxf(acc[ma][na][rh * 2], acc[ma][na][rh * 2 + 1]));
                m = fmaxf(m, __shfl_xor_sync(0xffffffffu, m, 1));
                m = fmaxf(m, __shfl_xor_sync(0xffffffffu, m, 2));
                if ((lane & 3) == 0)
                    smax[mgrp][ma * 16 + rh * 8 + (lane >> 2)][ng] = m;
            }
        __syncthreads();
#pragma unroll
        for (int ma = 0; ma < 2; ma++)
#pragma unroll
            for (int rh = 0; rh < 2; rh++) {
                int rrow = ma * 16 + rh * 8 + (lane >> 2);
                float gm = fmaxf(fmaxf(smax[mgrp][rrow][0], smax[mgrp][rrow][1]),
                                 fmaxf(smax[mgrp][rrow][2], smax[mgrp][rrow][3]));
                float s = 0.f;
#pragma unroll
                for (int na = 0; na < 16; na++) {
                    float e0 = __expf(acc[ma][na][rh * 2]     - gm);
                    float e1 = __expf(acc[ma][na][rh * 2 + 1] - gm);
                    acc[ma][na][rh * 2]     = e0;
                    acc[ma][na][rh * 2 + 1] = e1;
                    s += e0 + e1;
                }
                s += __shfl_xor_sync(0xffffffffu, s, 1);
                s += __shfl_xor_sync(0xffffffffu, s, 2);
                if ((lane & 3) == 0)
                    ssum[mgrp][rrow][ng] = s;
            }
        __syncthreads();
#pragma unroll
        for (int ma = 0; ma < 2; ma++)
#pragma unroll
            for (int rh = 0; rh < 2; rh++) {
                int rrow = ma * 16 + rh * 8 + (lane >> 2);
                float gs = ssum[mgrp][rrow][0] + ssum[mgrp][rrow][1] +
                           ssum[mgrp][rrow][2] + ssum[mgrp][rrow][3];
                inv_[ma][rh] = 1.f / gs;
            }
#pragma unroll
        for (int ma = 0; ma < 2; ma++)
#pragma unroll
            for (int na = 0; na < 16; na++)
#pragma unroll
                for (int rh = 0; rh < 2; rh++) {
                    acc[ma][na][rh * 2]     *= inv_[ma][rh];
                    acc[ma][na][rh * 2 + 1] *= inv_[ma][rh];
                }
    }

    float oacc[2][8][4];
#pragma unroll
    for (int i = 0; i < 2; i++)
#pragma unroll
        for (int j = 0; j < 8; j++)
#pragma unroll
            for (int q = 0; q < 4; q++) oacc[i][j][q] = 0.f;

    const uint32_t uVh = smem_u32(Vh), uVl = smem_u32(Vl);
#pragma unroll
    for (int j = 0; j < 8; j++) {
        uint32_t ah2[2][4], al2[2][4];
#pragma unroll
        for (int ma = 0; ma < 2; ma++) {
            split_pack(acc[ma][2 * j][0],     acc[ma][2 * j][1],     ah2[ma][0], al2[ma][0]);
            split_pack(acc[ma][2 * j][2],     acc[ma][2 * j][3],     ah2[ma][1], al2[ma][1]);
            split_pack(acc[ma][2 * j + 1][0], acc[ma][2 * j + 1][1], ah2[ma][2], al2[ma][2]);
            split_pack(acc[ma][2 * j + 1][2], acc[ma][2 * j + 1][3], ah2[ma][3], al2[ma][3]);
        }
        uint32_t bh[8][2], bl[8][2];
#pragma unroll
        for (int p = 0; p < 4; p++) {
            uint32_t rowB = p * 16 + hb * 8 + r8;
            uint32_t cb = (ng * 128 + j * 16 + sel * 8) * 2;
            uint32_t t[4];
            ldm4(t, uVh + rowB * VSTR + cb);
            bh[2 * p][0] = t[0]; bh[2 * p][1] = t[1];
            bh[2 * p + 1][0] = t[2]; bh[2 * p + 1][1] = t[3];
            ldm4(t, uVl + rowB * VSTR + cb);
            bl[2 * p][0] = t[0]; bl[2 * p][1] = t[1];
            bl[2 * p + 1][0] = t[2]; bl[2 * p + 1][1] = t[3];
        }
#pragma unroll
        for (int ma = 0; ma < 2; ma++)
#pragma unroll
            for (int q = 0; q < 8; q++)
                mma_bf16(oacc[ma][q], ah2[ma], bh[q]);
#pragma unroll
        for (int ma = 0; ma < 2; ma++)
#pragma unroll
            for (int q = 0; q < 8; q++)
                mma_bf16(oacc[ma][q], ah2[ma], bl[q]);
#pragma unroll
        for (int ma = 0; ma < 2; ma++)
#pragma unroll
            for (int q = 0; q < 8; q++)
                mma_bf16(oacc[ma][q], al2[ma], bh[q]);
    }

    for (int w = 0; w < 4; w++) {
        __syncthreads();
        if (ng == w) {
#pragma unroll
            for (int ma = 0; ma < 2; ma++)
#pragma unroll
                for (int na = 0; na < 8; na++)
#pragma unroll
                    for (int q = 0; q < 4; q++) {
                        int row = mgrp * 32 + ma * 16 + (lane >> 2) + (q >> 1) * 8;
                        int col = na * 8 + (lane & 3) * 2 + (q & 1);
                        smO[row * 64 + col] += oacc[ma][na][q];
                    }
        }
    }
    __syncthreads();

#pragma unroll
    for (int it = 0; it < 16; it++) {
        int idx = tid + it * 256;
        int r = idx >> 6, d = idx & 63;
        mgout[(long long)b * S_ * D_ + (long long)(s0 + r) * D_ + h * HD_ + d] = smO[idx];
    }
}

// ============================================================================
// V^T per (b,h) -> bf16 hi/lo planes (round-15 champion)
// ============================================================================
__global__ void transposeVp(const float* __restrict__ qkv,
                            bf16* __restrict__ vth, bf16* __restrict__ vtl)
{
    __shared__ bf16 th[32][33], tl[32][33];
    int z = blockIdx.z;
    int s0 = blockIdx.x * 32, d0 = blockIdx.y * 32;
    int b = z >> 3, h = z & 7;
    const float* src = qkv + (long long)b * S_ * 3 * D_ + 2 * D_ + h * HD_;
    int tx = threadIdx.x, ty = threadIdx.y;
#pragma unroll
    for (int r = 0; r < 4; r++) {
        int s = s0 + ty + r * 8;
        float v = src[(long long)s * (3 * D_) + d0 + tx];
        bf16 hi = __float2bfloat16_rn(v);
        bf16 lo = __float2bfloat16_rn(v - __bfloat162float(hi));
        th[ty + r * 8][tx] = hi;
        tl[ty + r * 8][tx] = lo;
    }
    __syncthreads();
    long long dbase = (long long)z * HD_ * S_;
#pragma unroll
    for (int r = 0; r < 4; r++) {
        int d = d0 + ty + r * 8;
        vth[dbase + (long long)d * S_ + s0 + tx] = th[tx][ty + r * 8];
        vtl[dbase + (long long)d * S_ + s0 + tx] = tl[tx][ty + r * 8];
    }
}

// ---------------- y = LayerNorm(t) * g + b ----------------
__global__ __launch_bounds__(128)
void ln_only(const float* __restrict__ t_in,
             const float* __restrict__ g, const float* __restrict__ b,
             float* __restrict__ y)
{
    long long row = blockIdx.x;
    int t = threadIdx.x;
    float4 a = ((const float4*)(t_in + row * D_))[t];

    float sum = a.x + a.y + a.z + a.w;
    float sq  = a.x * a.x + a.y * a.y + a.z * a.z + a.w * a.w;
#pragma unroll
    for (int off = 16; off > 0; off >>= 1) {
        sum += __shfl_xor_sync(0xffffffffu, sum, off);
        sq  += __shfl_xor_sync(0xffffffffu, sq,  off);
    }
    __shared__ float s1[4], s2[4];
    if ((t & 31) == 0) { s1[t >> 5] = sum; s2[t >> 5] = sq; }
    __syncthreads();
    sum = s1[0] + s1[1] + s1[2] + s1[3];
    sq  = s2[0] + s2[1] + s2[2] + s2[3];

    float mean = sum * (1.f / D_);
    float var  = sq * (1.f / D_) - mean * mean;
    float inv  = rsqrtf(var + 1e-5f);

    float4 gg = ((const float4*)g)[t];
    float4 bb = ((const float4*)b)[t];
    float4 o;
    o.x = (a.x - mean) * inv * gg.x + bb.x;
    o.y = (a.y - mean) * inv * gg.y + bb.y;
    o.z = (a.z - mean) * inv * gg.z + bb.z;
    o.w = (a.w - mean) * inv * gg.w + bb.w;
    ((float4*)(y + row * D_))[t] = o;
}

// ---------------- small fp32 SGEMM (tail + head): C = A@B^T + bias [+R], relu ----
#define BMH 128
#define BNH 128
#define BKH 8
template<bool BIAS, bool RELU, bool RES>
__global__ __launch_bounds__(256)
void sgemm32(const float* __restrict__ A, const float* __restrict__ B,
             const float* __restrict__ bias, const float* __restrict__ R,
             float* __restrict__ C,
             int M, int N, int K, int lda, int ldb, int ldr, int ldc)
{
    __shared__ float As[BKH][BMH];
    __shared__ float Bs[BKH][BNH];
    const int m0 = blockIdx.y * BMH;
    const int n0 = blockIdx.x * BNH;
    const int tid = threadIdx.x;
    const int arow = tid >> 1;
    const int acol = (tid & 1) * 4;
    const int tx = tid & 15;
    const int ty = tid >> 4;

    float acc[8][8];
#pragma unroll
    for (int i = 0; i < 8; i++)
#pragma unroll
        for (int j = 0; j < 8; j++) acc[i][j] = 0.f;

    for (int k0 = 0; k0 < K; k0 += BKH) {
        float4 av = make_float4(0.f, 0.f, 0.f, 0.f);
        if (m0 + arow < M)
            av = *(const float4*)&A[(long long)(m0 + arow) * lda + k0 + acol];
        As[acol + 0][arow] = av.x; As[acol + 1][arow] = av.y;
        As[acol + 2][arow] = av.z; As[acol + 3][arow] = av.w;
        float4 bv = make_float4(0.f, 0.f, 0.f, 0.f);
        if (n0 + arow < N)
            bv = *(const float4*)&B[(long long)(n0 + arow) * ldb + k0 + acol];
        Bs[acol + 0][arow] = bv.x; Bs[acol + 1][arow] = bv.y;
        Bs[acol + 2][arow] = bv.z; Bs[acol + 3][arow] = bv.w;
        __syncthreads();
#pragma unroll
        for (int kk = 0; kk < BKH; kk++) {
            float a[8], b[8];
            *(float4*)&a[0] = *(const float4*)&As[kk][ty * 8];
            *(float4*)&a[4] = *(const float4*)&As[kk][ty * 8 + 4];
            *(float4*)&b[0] = *(const float4*)&Bs[kk][tx * 8];
            *(float4*)&b[4] = *(const float4*)&Bs[kk][tx * 8 + 4];
#pragma unroll
            for (int i = 0; i < 8; i++)
#pragma unroll
                for (int j = 0; j < 8; j++)
                    acc[i][j] += a[i] * b[j];
        }
        __syncthreads();
    }
#pragma unroll
    for (int i = 0; i < 8; i++) {
        int row = m0 + ty * 8 + i;
        if (row >= M) continue;
#pragma unroll
        for (int j = 0; j < 8; j++) {
            int col = n0 + tx * 8 + j;
            if (col >= N) continue;
            float v = acc[i][j];
            if (BIAS) v += bias[col];
            if (RELU) v = fmaxf(v, 0.f);
            if (RES)  v += R[(long long)row * ldr + col];
            C[(long long)row * ldc + col] = v;
        }
    }
}

// ---------------- final head ----------------
__global__ __launch_bounds__(256)
void head_out(const float* __restrict__ h, const float* __restrict__ w2,
              const float* __restrict__ b2, float* __restrict__ out)
{
    int m = blockIdx.x;
    int t = threadIdx.x;
    float s = 0.f;
    for (int k = t; k < FF_; k += 256)
        s += h[m * FF_ + k] * w2[k];
#pragma unroll
    for (int off = 16; off > 0; off >>= 1)
        s += __shfl_xor_sync(0xffffffffu, s, off);
    __shared__ float sm[8];
    if ((t & 31) == 0) sm[t >> 5] = s;
    __syncthreads();
    if (t == 0) {
        float tot = 0.f;
#pragma unroll
        for (int w = 0; w < 8; w++) tot += sm[w];
        out[m] = tot + b2[0];
    }
}

// ---------------- orchestration ----------------
static constexpr int STAGE128 = 2 * ASZ + 2 * 128 * RSTR;  // 40960
static constexpr int SMEM_128 = 2 * STAGE128;               // 81920

extern "C" void kernel_launch(void* const* d_in, const int* in_sizes, int n_in,
                              void* d_out, int out_size)
{
    const float* src       = (const float*)d_in[0];
    const float* inp_w     = (const float*)d_in[1];
    const float* inp_b     = (const float*)d_in[2];
    const float* in_proj_w = (const float*)d_in[3];
    const float* in_proj_b = (const float*)d_in[4];
    const float* out_w     = (const float*)d_in[5];
    const float* out_b     = (const float*)d_in[6];
    const float* ff_w1     = (const float*)d_in[7];
    const float* ff_b1     = (const float*)d_in[8];
    const float* ff_w2     = (const float*)d_in[9];
    const float* ff_b2     = (const float*)d_in[10];
    const float* ln1_g     = (const float*)d_in[11];
    const float* ln1_b     = (const float*)d_in[12];
    const float* ln2_g     = (const float*)d_in[13];
    const float* ln2_b     = (const float*)d_in[14];
    const float* op_w1     = (const float*)d_in[15];
    const float* op_b1     = (const float*)d_in[16];
    const float* op_w2     = (const float*)d_in[17];
    const float* op_b2     = (const float*)d_in[18];
    float* out = (float*)d_out;

    float *x, *big, *att, *mg, *hh, *t32, *x32;
    bf16 *wh, *wl, *vth, *vtl;
    cudaGetSymbolAddress((void**)&x,   g_x);
    cudaGetSymbolAddress((void**)&big, g_big);
    cudaGetSymbolAddress((void**)&att, g_att);
    cudaGetSymbolAddress((void**)&mg,  g_m);
    cudaGetSymbolAddress((void**)&hh,  g_h);
    cudaGetSymbolAddress((void**)&t32, g_t32);
    cudaGetSymbolAddress((void**)&x32, g_x32);
    cudaGetSymbolAddress((void**)&wh,  g_wh);
    cudaGetSymbolAddress((void**)&wl,  g_wl);
    cudaGetSymbolAddress((void**)&vth, g_vth);
    cudaGetSymbolAddress((void**)&vtl, g_vtl);

    cudaFuncSetAttribute(gemm_w<true, false, false, false>, cudaFuncAttributeMaxDynamicSharedMemorySize, SMEM_128);
    cudaFuncSetAttribute(gemm_w<true, true,  false, false>, cudaFuncAttributeMaxDynamicSharedMemorySize, SMEM_128);
    cudaFuncSetAttribute(gemm_w<true, false, true,  false>, cudaFuncAttributeMaxDynamicSharedMemorySize, SMEM_128);
    cudaFuncSetAttribute(gemm_w<true, false, false, true >, cudaFuncAttributeMaxDynamicSharedMemorySize, SMEM_128);
    cudaFuncSetAttribute(flash_attn, cudaFuncAttributeMaxDynamicSharedMemorySize, FL_SMEM);

    // ---- pre-split all weights into bf16 hi/lo planes ----
    cvt_plane<<<(32768 / 4 + 255) / 256, 256>>>(
        (const float4*)inp_w, (bf162*)(wh + OFF_INPW), (bf162*)(wl + OFF_INPW), 32768 / 4);
    cvt_plane<<<(4718592 / 4 + 255) / 256, 256>>>(
        (const float4*)in_proj_w, (bf162*)(wh + OFF_INPROJ), (bf162*)(wl + OFF_INPROJ), 4718592 / 4);
    cvt_plane<<<(1572864 / 4 + 255) / 256, 256>>>(
        (const float4*)out_w, (bf162*)(wh + OFF_OUTW), (bf162*)(wl + OFF_OUTW), 1572864 / 4);
    cvt_plane<<<(6291456 / 4 + 255) / 256, 256>>>(
        (const float4*)ff_w1, (bf162*)(wh + OFF_FF1), (bf162*)(wl + OFF_FF1), 6291456 / 4);
    cvt_plane<<<(6291456 / 4 + 255) / 256, 256>>>(
        (const float4*)ff_w2, (bf162*)(wh + OFF_FF2), (bf162*)(wl + OFF_FF2), 6291456 / 4);

    // input projection with fused positional encoding
    gemm_w<true, false, false, true><<<dim3(4, 128, 1), 256, SMEM_128>>>(
        src, wh + OFF_INPW, wl + OFF_INPW, inp_b, nullptr, x,
        IN_, IN_, IN_, D_, 22.62741699796952f, 128, 0);

    // ---- layers 0..4: full path (byte-identical to round-15 champion) ----
    for (int i = 0; i < L_ - 1; i++) {
        const long long wq = OFF_INPROJ + (long long)i * 3 * D_ * D_;
        const long long wo = OFF_OUTW   + (long long)i * D_ * D_;
        const long long w1 = OFF_FF1    + (long long)i * FF_ * D_;
        const long long w2 = OFF_FF2    + (long long)i * D_ * FF_;

        gemm_w<true, false, false, false><<<dim3(12, 128, 1), 256, SMEM_128>>>(
            x, wh + wq, wl + wq, in_proj_b + i * 3 * D_, nullptr, big,
            D_, D_, D_, 3 * D_, 1.f, 128, 0);

        transposeVp<<<dim3(16, 2, NBH), dim3(32, 8)>>>(big, vth, vtl);
        flash_attn<<<dim3(8, NBH), 256, FL_SMEM>>>(big, vth, vtl, mg, 0);

        gemm_w<true, false, true, false><<<dim3(4, 128, 1), 256, SMEM_128>>>(
            mg, wh + wo, wl + wo, out_b + i * D_, x, att,
            D_, D_, D_, D_, 1.f, 128, 0);
        ln_only<<<MROWS, 128>>>(att, ln1_g + i * D_, ln1_b + i * D_, x);

        gemm_w<true, true, false, false><<<dim3(16, 128, 1), 256, SMEM_128>>>(
            x, wh + w1, wl + w1, ff_b1 + i * FF_, nullptr, big,
            D_, D_, D_, FF_, 1.f, 128, 0);
        gemm_w<true, false, true, false><<<dim3(4, 128, 1), 256, SMEM_128>>>(
            big, wh + w2, wl + w2, ff_b2 + i * D_, x, att,
            FF_, FF_, FF_, D_, 1.f, 128, 0);
        ln_only<<<MROWS, 128>>>(att, ln2_g + i * D_, ln2_b + i * D_, x);
    }

    // ---- layer 5: only last-token rows are live downstream ----
    {
        const int i = L_ - 1;
        const long long wq = OFF_INPROJ + (long long)i * 3 * D_ * D_;

        // qkv K,V columns (512..1536) for all rows
        gemm_w<true, false, false, false><<<dim3(8, 128, 1), 256, SMEM_128>>>(
            x, wh + wq + (long long)D_ * D_, wl + wq + (long long)D_ * D_,
            in_proj_b + i * 3 * D_ + D_, nullptr, big + D_,
            D_, D_, D_, 3 * D_, 1.f, 128, 0);
        // qkv Q columns (0..512) only for rows 384..511 of each batch
        gemm_w<true, false, false, false><<<dim3(4, 32, 1), 256, SMEM_128>>>(
            x, wh + wq, wl + wq, in_proj_b + i * 3 * D_, nullptr, big,
            D_, D_, D_, 3 * D_, 1.f, 512, 384);

        transposeVp<<<dim3(16, 2, NBH), dim3(32, 8)>>>(big, vth, vtl);
        // only the last q-block (rows 448..511) per (b,h)
        flash_attn<<<dim3(1, NBH), 256, FL_SMEM>>>(big, vth, vtl, mg, 448);

        // tail on the 32 last-token rows, fp32 (layer-5 original weights)
        // t32 = mg[last] @ out_w[5]^T + out_b[5] + x[last]
        sgemm32<true, false, true><<<dim3(4, 1, 1), 256>>>(
            mg + (S_ - 1) * D_, out_w + (long long)i * D_ * D_,
            out_b + i * D_, x + (S_ - 1) * D_, t32,
            B_, D_, D_, S_ * D_, D_, S_ * D_, D_);
        ln_only<<<B_, 128>>>(t32, ln1_g + i * D_, ln1_b + i * D_, x32);
        // hh = relu(x32 @ ff_w1[5]^T + b1)
        sgemm32<true, true, false><<<dim3(16, 1, 1), 256>>>(
            x32, ff_w1 + (long long)i * FF_ * D_, ff_b1 + i * FF_, nullptr, hh,
            B_, FF_, D_, D_, D_, 0, FF_);
        // t32 = hh @ ff_w2[5]^T + b2 + x32
        sgemm32<true, false, true><<<dim3(4, 1, 1), 256>>>(
            hh, ff_w2 + (long long)i * D_ * FF_, ff_b2 + i * D_, x32, t32,
            B_, D_, FF_, FF_, FF_, D_, D_);
        ln_only<<<B_, 128>>>(t32, ln2_g + i * D_, ln2_b + i * D_, x32);
    }

    // head: hh = relu(x32 @ op_w1^T + op_b1); out = hh @ op_w2^T + op_b2
    sgemm32<true, true, false><<<dim3(16, 1, 1), 256>>>(
        x32, op_w1, op_b1, nullptr, hh, B_, FF_, D_, D_, D_, 0, FF_);
    head_out<<<B_, 256>>>(hh, op_w2, op_b2, out);
}